// round 11
// baseline (speedup 1.0000x reference)
#include <cuda_runtime.h>
#include <cuda_bf16.h>
#include <math.h>

#define NN 1024
#define DIM 512
#define QKVD 1536
#define HEADS 8
#define HD 64
#define BM 64
#define NSPLIT 2
#define MPART (NN / NSPLIT)

#define QKV_MT 128
#define QKV_NT 64
#define QKV_BLOCKS ((NN / QKV_MT) * (QKVD / QKV_NT))   // 192

// Scratch (static device allocation only).
__device__ float g_qkv[NN * QKVD];
__device__ float g_S[(size_t)HEADS * NN * NN];
__device__ float g_Op[NSPLIT][HEADS][NN][HD];
__device__ float g_mx[NSPLIT][HEADS][NN];
__device__ float g_ls[NSPLIT][HEADS][NN];
__device__ float g_ptab[NN * 32];   // per-box phases: [b][w|h][j][sin|cos]

// ---------------------------------------------------------------------------
// helpers
// ---------------------------------------------------------------------------
__device__ __forceinline__ unsigned cvt_tf32(float f) {
    unsigned u;
    asm("cvt.rna.tf32.f32 %0, %1;" : "=r"(u) : "f"(f));
    return u;
}
__device__ __forceinline__ void split_tf32(float f, unsigned& hi, unsigned& lo) {
    hi = cvt_tf32(f);
    lo = cvt_tf32(f - __uint_as_float(hi));
}
__device__ __forceinline__ void mma_tf32(float* c, const unsigned* a, const unsigned* b) {
    asm volatile(
        "mma.sync.aligned.m16n8k8.row.col.f32.tf32.tf32.f32 "
        "{%0,%1,%2,%3}, {%4,%5,%6,%7}, {%8,%9}, {%0,%1,%2,%3};"
        : "+f"(c[0]), "+f"(c[1]), "+f"(c[2]), "+f"(c[3])
        : "r"(a[0]), "r"(a[1]), "r"(a[2]), "r"(a[3]), "r"(b[0]), "r"(b[1]));
}
__device__ __forceinline__ void mma_bf16(float* c, const unsigned* a, const unsigned* b) {
    asm volatile(
        "mma.sync.aligned.m16n8k16.row.col.f32.bf16.bf16.f32 "
        "{%0,%1,%2,%3}, {%4,%5,%6,%7}, {%8,%9}, {%0,%1,%2,%3};"
        : "+f"(c[0]), "+f"(c[1]), "+f"(c[2]), "+f"(c[3])
        : "r"(a[0]), "r"(a[1]), "r"(a[2]), "r"(a[3]), "r"(b[0]), "r"(b[1]));
}
// pack two floats to bf16x2: lower half = first arg (even k), upper = second
__device__ __forceinline__ unsigned bfpack(float lo_e, float hi_e) {
    unsigned r;
    asm("cvt.rn.bf16x2.f32 %0, %1, %2;" : "=r"(r) : "f"(hi_e), "f"(lo_e));
    return r;
}
__device__ __forceinline__ float bfres(float f) {
    return f - __bfloat162float(__float2bfloat16(f));
}

// ---------------------------------------------------------------------------
// K0: per-box phase table for the separable dw/dh feature groups.
// g_ptab[b*32 + 2j]   = sin(f_j log w_b),  [+1] = cos;  [16..] same for h.
// ---------------------------------------------------------------------------
__global__ void __launch_bounds__(256) phase_tab(const float* __restrict__ locs) {
    const int b = blockIdx.x * 256 + threadIdx.x;
    const float4 bx = ((const float4*)locs)[b];
    const float lw = __logf(bx.z - bx.x + 1.0f);
    const float lh = __logf(bx.w - bx.y + 1.0f);
    const float invd[8] = {100.0f, 42.1696503f, 17.7827941f, 7.49894209f,
                           3.16227766f, 1.33352143f, 0.562341325f, 0.237137371f};
#pragma unroll
    for (int j = 0; j < 8; j++) {
        float s, c;
        __sincosf(lw * invd[j], &s, &c);
        g_ptab[b * 32 + 2 * j] = s;
        g_ptab[b * 32 + 2 * j + 1] = c;
        __sincosf(lh * invd[j], &s, &c);
        g_ptab[b * 32 + 16 + 2 * j] = s;
        g_ptab[b * 32 + 16 + 2 * j + 1] = c;
    }
}

// ---------------------------------------------------------------------------
// K1: tf32 QKV GEMM. 128x64 tile, 8 warps (4m x 2n).
// ---------------------------------------------------------------------------
__global__ void __launch_bounds__(256) qkv_gemm(const float* __restrict__ x,
                                                const float* __restrict__ W) {
    __shared__ float As[QKV_MT][20];
    __shared__ float Bs[QKV_NT][20];
    const int t = threadIdx.x;
    const int qb = blockIdx.x;
    const int bm = (qb % (NN / QKV_MT)) * QKV_MT;
    const int bn = (qb / (NN / QKV_MT)) * QKV_NT;
    const int w  = t >> 5, l = t & 31;
    const int wm = (w & 3) * 32;
    const int wn = (w >> 2) * 32;
    const int lq = l >> 2, lr = l & 3;

    const int arow = t >> 1;
    const int akc  = (t & 1) * 8;
    const float* Ap = x + (size_t)(bm + arow) * DIM + akc;
    const float* Bp = W + (size_t)(bn + (arow & 63)) * DIM + akc;

    float4 ra0 = *(const float4*)Ap;
    float4 ra1 = *(const float4*)(Ap + 4);
    float4 rb0 = make_float4(0, 0, 0, 0), rb1 = rb0;
    if (t < 128) { rb0 = *(const float4*)Bp; rb1 = *(const float4*)(Bp + 4); }

    float acc[2][4][4] = {};

    for (int kk = 0; kk < DIM; kk += 16) {
        __syncthreads();
        *(float4*)&As[arow][akc]     = ra0;
        *(float4*)&As[arow][akc + 4] = ra1;
        if (t < 128) {
            *(float4*)&Bs[arow & 63][akc]     = rb0;
            *(float4*)&Bs[arow & 63][akc + 4] = rb1;
        }
        __syncthreads();
        if (kk + 16 < DIM) {
            ra0 = *(const float4*)(Ap + kk + 16);
            ra1 = *(const float4*)(Ap + kk + 20);
            if (t < 128) {
                rb0 = *(const float4*)(Bp + kk + 16);
                rb1 = *(const float4*)(Bp + kk + 20);
            }
        }
#pragma unroll
        for (int ks = 0; ks < 16; ks += 8) {
            unsigned ahi[2][4], alo[2][4];
#pragma unroll
            for (int mi = 0; mi < 2; mi++) {
                const int r = wm + mi * 16;
                split_tf32(As[r + lq][ks + lr],          ahi[mi][0], alo[mi][0]);
                split_tf32(As[r + lq + 8][ks + lr],      ahi[mi][1], alo[mi][1]);
                split_tf32(As[r + lq][ks + lr + 4],      ahi[mi][2], alo[mi][2]);
                split_tf32(As[r + lq + 8][ks + lr + 4],  ahi[mi][3], alo[mi][3]);
            }
#pragma unroll
            for (int ni = 0; ni < 4; ni++) {
                unsigned bhi[2], blo[2];
                const int c = wn + ni * 8 + lq;
                split_tf32(Bs[c][ks + lr],     bhi[0], blo[0]);
                split_tf32(Bs[c][ks + lr + 4], bhi[1], blo[1]);
#pragma unroll
                for (int mi = 0; mi < 2; mi++) {
                    mma_tf32(acc[mi][ni], ahi[mi], bhi);
                    mma_tf32(acc[mi][ni], ahi[mi], blo);
                    mma_tf32(acc[mi][ni], alo[mi], bhi);
                }
            }
        }
    }
#pragma unroll
    for (int mi = 0; mi < 2; mi++)
#pragma unroll
        for (int ni = 0; ni < 4; ni++) {
            const int r = bm + wm + mi * 16 + lq;
            const int c = bn + wn + ni * 8 + lr * 2;
            *(float2*)&g_qkv[(size_t)r * QKVD + c] =
                make_float2(acc[mi][ni][0], acc[mi][ni][1]);
            *(float2*)&g_qkv[(size_t)(r + 8) * QKVD + c] =
                make_float2(acc[mi][ni][2], acc[mi][ni][3]);
        }
}

// ---------------------------------------------------------------------------
// K2: location bias, tensor-core head projection + phase-table dw/dh groups.
// ---------------------------------------------------------------------------
#define LSTR 20   // u32 stride of emb staging rows (conflict-free)

__global__ void __launch_bounds__(256, 3) loc_bias(const float* __restrict__ locs,
                                                   const float* __restrict__ Wl,
                                                   const float* __restrict__ bl) {
    __shared__ unsigned semb[8][2][32 * LSTR];  // [warp][hi|lo][row*LSTR + ku]
    __shared__ float sb[8];
    __shared__ float s_nph[32];                 // n-box phases (w,h)
    const int t = threadIdx.x;
    const int w = t >> 5, l = t & 31;
    const int lq = l >> 2, lr = l & 3;

    const int n = blockIdx.x >> 2;
    const int mb = (blockIdx.x & 3) * 256;
    const int m = mb + t;

    if (t < 8) sb[t] = bl[t];
    if (t < 32) s_nph[t] = g_ptab[n * 32 + t];

    // W fragments (B of mma, col = head = lq)
    unsigned whi[4][2], wlo[4][2];
#pragma unroll
    for (int s = 0; s < 4; s++) {
        const float* wp = Wl + lq * 64 + s * 16 + 2 * lr;
        float w00 = wp[0], w01 = wp[1], w10 = wp[8], w11 = wp[9];
        whi[s][0] = bfpack(w00, w01);
        wlo[s][0] = bfpack(bfres(w00), bfres(w01));
        whi[s][1] = bfpack(w10, w11);
        wlo[s][1] = bfpack(bfres(w10), bfres(w11));
    }
    __syncthreads();

    const float4 bn = ((const float4*)locs)[n];
    const float4 bm = ((const float4*)locs)[m];
    const float wn = bn.z - bn.x + 1.0f, hn = bn.w - bn.y + 1.0f;
    const float cxn = 0.5f * (bn.x + bn.z), cyn = 0.5f * (bn.y + bn.w);
    const float cxm = 0.5f * (bm.x + bm.z), cym = 0.5f * (bm.y + bm.w);

    float pos[2];
    pos[0] = __logf(fmaxf(fabsf((cxn - cxm) / wn), 1e-3f));
    pos[1] = __logf(fmaxf(fabsf((cyn - cym) / hn), 1e-3f));

    const float invd[8] = {100.0f, 42.1696503f, 17.7827941f, 7.49894209f,
                           3.16227766f, 1.33352143f, 0.562341325f, 0.237137371f};

    // Accumulators: c[mtile][4]; cols = heads 2lr, 2lr+1; rows = pairs.
    float c[2][4];
#pragma unroll
    for (int mi = 0; mi < 2; mi++) {
        c[mi][0] = sb[2 * lr];     c[mi][1] = sb[2 * lr + 1];
        c[mi][2] = sb[2 * lr];     c[mi][3] = sb[2 * lr + 1];
    }

    unsigned* sh = semb[w][0];
    unsigned* sl = semb[w][1];

#pragma unroll
    for (int ph = 0; ph < 2; ph++) {
        unsigned hi[16], lo[16];
        if (ph == 0) {
            // g=0,1 (dx, dy): true sincos
            float e[32];
#pragma unroll
            for (int gg = 0; gg < 2; gg++) {
                const float pg = pos[gg];
#pragma unroll
                for (int j = 0; j < 8; j++)
                    __sincosf(pg * invd[j], &e[gg * 16 + j], &e[gg * 16 + 8 + j]);
            }
#pragma unroll
            for (int u = 0; u < 16; u++) {
                hi[u] = bfpack(e[2 * u], e[2 * u + 1]);
                lo[u] = bfpack(bfres(e[2 * u]), bfres(e[2 * u + 1]));
            }
        } else {
            // g=2,3 (dw, dh): angle addition from phase table
#pragma unroll
            for (int half = 0; half < 2; half++) {
                const float* tp = &g_ptab[m * 32 + half * 16];
                float4 t0 = *(const float4*)(tp + 0);
                float4 t1 = *(const float4*)(tp + 4);
                float4 t2 = *(const float4*)(tp + 8);
                float4 t3 = *(const float4*)(tp + 12);
                const float sm8[8] = {t0.x, t0.z, t1.x, t1.z, t2.x, t2.z, t3.x, t3.z};
                const float cm8[8] = {t0.y, t0.w, t1.y, t1.w, t2.y, t2.w, t3.y, t3.w};
                float s8[8], c8[8];
#pragma unroll
                for (int j = 0; j < 8; j++) {
                    const float sn_ = s_nph[half * 16 + 2 * j];
                    const float cn_ = s_nph[half * 16 + 2 * j + 1];
                    s8[j] = sm8[j] * cn_ - cm8[j] * sn_;
                    c8[j] = cm8[j] * cn_ + sm8[j] * sn_;
                }
#pragma unroll
                for (int u = 0; u < 4; u++) {
                    hi[half * 8 + u]     = bfpack(s8[2 * u], s8[2 * u + 1]);
                    lo[half * 8 + u]     = bfpack(bfres(s8[2 * u]), bfres(s8[2 * u + 1]));
                    hi[half * 8 + 4 + u] = bfpack(c8[2 * u], c8[2 * u + 1]);
                    lo[half * 8 + 4 + u] = bfpack(bfres(c8[2 * u]), bfres(c8[2 * u + 1]));
                }
            }
        }
        __syncwarp();  // previous phase's frag reads complete
        const int rb = l * LSTR;
#pragma unroll
        for (int q = 0; q < 4; q++) {
            *(uint4*)&sh[rb + q * 4] = make_uint4(hi[q*4], hi[q*4+1], hi[q*4+2], hi[q*4+3]);
            *(uint4*)&sl[rb + q * 4] = make_uint4(lo[q*4], lo[q*4+1], lo[q*4+2], lo[q*4+3]);
        }
        __syncwarp();

#pragma unroll
        for (int s2 = 0; s2 < 2; s2++) {
            const int s = ph * 2 + s2;
#pragma unroll
            for (int mi = 0; mi < 2; mi++) {
                const int r0 = (mi * 16 + lq) * LSTR + s2 * 8 + lr;
                const int r1 = (mi * 16 + lq + 8) * LSTR + s2 * 8 + lr;
                unsigned ah[4] = {sh[r0], sh[r1], sh[r0 + 4], sh[r1 + 4]};
                unsigned al[4] = {sl[r0], sl[r1], sl[r0 + 4], sl[r1 + 4]};
                mma_bf16(c[mi], ah, whi[s]);
                mma_bf16(c[mi], ah, wlo[s]);
                mma_bf16(c[mi], al, whi[s]);
            }
        }
    }

    // Write: thread owns heads 2lr,2lr+1 at pairs (w*32 + mi*16 + lq) and +8.
    const int h0 = 2 * lr, h1 = 2 * lr + 1;
#pragma unroll
    for (int mi = 0; mi < 2; mi++) {
        const size_t m0 = (size_t)n * NN + mb + w * 32 + mi * 16 + lq;
        const size_t m1 = m0 + 8;
        g_S[(size_t)h0 * NN * NN + m0] = __logf(fmaxf(c[mi][0], 0.0f) + 1e-6f);
        g_S[(size_t)h1 * NN * NN + m0] = __logf(fmaxf(c[mi][1], 0.0f) + 1e-6f);
        g_S[(size_t)h0 * NN * NN + m1] = __logf(fmaxf(c[mi][2], 0.0f) + 1e-6f);
        g_S[(size_t)h1 * NN * NN + m1] = __logf(fmaxf(c[mi][3], 0.0f) + 1e-6f);
    }
}

// ---------------------------------------------------------------------------
// K3: split-KV flash attention, bf16x2 hi/lo 3-pass, mma m16n8k16.
// (no launch-bounds cap: let regs float; empirically faster than (256,2))
// ---------------------------------------------------------------------------
#define SQ2 36
#define A_Qh 0
#define A_Ql (64 * SQ2)
#define A_Kh (2 * 64 * SQ2)
#define A_Kl (3 * 64 * SQ2)
#define A_Vh (4 * 64 * SQ2)
#define A_Vl (5 * 64 * SQ2)
#define A_PM (6 * 64 * SQ2)
#define A_PS (A_PM + 128)
#define ATTN_SMEM_U32 (A_PS + 128)

__device__ __forceinline__ void load_split_row(const float* __restrict__ gp,
                                               unsigned* sh, unsigned* sl,
                                               int row, int quarter) {
    const float* p = gp + quarter * 16;
    float4 f0 = *(const float4*)p;
    float4 f1 = *(const float4*)(p + 4);
    float4 f2 = *(const float4*)(p + 8);
    float4 f3 = *(const float4*)(p + 12);
    const float f[16] = {f0.x, f0.y, f0.z, f0.w, f1.x, f1.y, f1.z, f1.w,
                         f2.x, f2.y, f2.z, f2.w, f3.x, f3.y, f3.z, f3.w};
    unsigned hi[8], lo[8];
#pragma unroll
    for (int j = 0; j < 8; j++) {
        hi[j] = bfpack(f[2 * j], f[2 * j + 1]);
        lo[j] = bfpack(bfres(f[2 * j]), bfres(f[2 * j + 1]));
    }
    const int a = row * SQ2 + quarter * 8;
    *(uint4*)&sh[a]     = make_uint4(hi[0], hi[1], hi[2], hi[3]);
    *(uint4*)&sh[a + 4] = make_uint4(hi[4], hi[5], hi[6], hi[7]);
    *(uint4*)&sl[a]     = make_uint4(lo[0], lo[1], lo[2], lo[3]);
    *(uint4*)&sl[a + 4] = make_uint4(lo[4], lo[5], lo[6], lo[7]);
}

__global__ void fused_attn() {
    extern __shared__ unsigned sm[];
    unsigned* sQh = sm + A_Qh;
    unsigned* sQl = sm + A_Ql;
    unsigned* sKh = sm + A_Kh;   // K in S phase; P in PV phase
    unsigned* sKl = sm + A_Kl;
    unsigned* sVh = sm + A_Vh;   // transposed: [d][mpair]
    unsigned* sVl = sm + A_Vl;
    float* pmax = (float*)(sm + A_PM);
    float* psum = (float*)(sm + A_PS);

    const int t = threadIdx.x;
    const int w = t >> 5, l = t & 31;
    const int lq = l >> 2, lr = l & 3;
    const int mrow = (w & 3) * 16;
    const int wn2  = w >> 2;
    const int ncol = wn2 * 32;

    const int h   = blockIdx.x & 7;
    const int qt  = (blockIdx.x >> 3) & 15;
    const int sp  = blockIdx.x >> 7;
    const int bm  = qt * BM;
    const int m0g = sp * MPART;

    const float* Qg = g_qkv + h * HD;
    const float* Kg = g_qkv + DIM + h * HD;
    const float* Vg = g_qkv + 2 * DIM + h * HD;
    const float* Bg = g_S + (size_t)h * NN * NN;

    {
        const int row = t >> 2;
        load_split_row(Qg + (size_t)(bm + row) * QKVD, sQh, sQl, row, t & 3);
    }

    float o[4][4] = {};
    float rmax0 = -INFINITY, rmax1 = -INFINITY;
    float rsum0 = 0.0f, rsum1 = 0.0f;

    for (int mt = 0; mt < MPART / 64; mt++) {
        const int mbase = m0g + mt * 64;
        __syncthreads();

        {
            const int row = t >> 2;
            load_split_row(Kg + (size_t)(mbase + row) * QKVD, sKh, sKl, row, t & 3);
        }
        {
            const int mp = t & 31;
            const int d0 = (t >> 5) * 8;
            const float* Vp0 = Vg + (size_t)(mbase + 2 * mp) * QKVD + d0;
            const float* Vp1 = Vp0 + QKVD;
            float4 a0 = *(const float4*)Vp0;
            float4 a1 = *(const float4*)(Vp0 + 4);
            float4 b0 = *(const float4*)Vp1;
            float4 b1 = *(const float4*)(Vp1 + 4);
            const float va[8] = {a0.x, a0.y, a0.z, a0.w, a1.x, a1.y, a1.z, a1.w};
            const float vb[8] = {b0.x, b0.y, b0.z, b0.w, b1.x, b1.y, b1.z, b1.w};
#pragma unroll
            for (int d = 0; d < 8; d++) {
                sVh[(d0 + d) * SQ2 + mp] = bfpack(va[d], vb[d]);
                sVl[(d0 + d) * SQ2 + mp] = bfpack(bfres(va[d]), bfres(vb[d]));
            }
        }
        float2 bia0[4], bia1[4];
#pragma unroll
        for (int ni = 0; ni < 4; ni++) {
            const size_t cb = (size_t)(bm + mrow + lq) * NN + mbase + ncol + ni * 8 + lr * 2;
            bia0[ni] = *(const float2*)(Bg + cb);
            bia1[ni] = *(const float2*)(Bg + cb + 8 * NN);
        }
        __syncthreads();

        float sc[4][4] = {};
#pragma unroll
        for (int s = 0; s < 4; s++) {
            const int ks2 = s * 8;
            unsigned ah[4], al_[4];
            const int ab = (mrow + lq) * SQ2 + ks2 + lr;
            ah[0] = sQh[ab];  ah[1] = sQh[ab + 8 * SQ2];
            ah[2] = sQh[ab + 4]; ah[3] = sQh[ab + 8 * SQ2 + 4];
            al_[0] = sQl[ab]; al_[1] = sQl[ab + 8 * SQ2];
            al_[2] = sQl[ab + 4]; al_[3] = sQl[ab + 8 * SQ2 + 4];
#pragma unroll
            for (int ni = 0; ni < 4; ni++) {
                const int bb = (ncol + ni * 8 + lq) * SQ2 + ks2 + lr;
                unsigned bh[2] = {sKh[bb], sKh[bb + 4]};
                unsigned bl[2] = {sKl[bb], sKl[bb + 4]};
                mma_bf16(sc[ni], ah, bh);
                mma_bf16(sc[ni], ah, bl);
                mma_bf16(sc[ni], al_, bh);
            }
        }

        float sv[4][4];
#pragma unroll
        for (int ni = 0; ni < 4; ni++) {
            sv[ni][0] = fmaf(0.125f, sc[ni][0], bia0[ni].x);
            sv[ni][1] = fmaf(0.125f, sc[ni][1], bia0[ni].y);
            sv[ni][2] = fmaf(0.125f, sc[ni][2], bia1[ni].x);
            sv[ni][3] = fmaf(0.125f, sc[ni][3], bia1[ni].y);
        }
        float mx0 = fmaxf(fmaxf(sv[0][0], sv[0][1]), fmaxf(sv[1][0], sv[1][1]));
        mx0 = fmaxf(mx0, fmaxf(fmaxf(sv[2][0], sv[2][1]), fmaxf(sv[3][0], sv[3][1])));
        float mx1 = fmaxf(fmaxf(sv[0][2], sv[0][3]), fmaxf(sv[1][2], sv[1][3]));
        mx1 = fmaxf(mx1, fmaxf(fmaxf(sv[2][2], sv[2][3]), fmaxf(sv[3][2], sv[3][3])));
#pragma unroll
        for (int off = 1; off <= 2; off <<= 1) {
            mx0 = fmaxf(mx0, __shfl_xor_sync(0xffffffffu, mx0, off));
            mx1 = fmaxf(mx1, __shfl_xor_sync(0xffffffffu, mx1, off));
        }
        if (lr == 0) {
            pmax[wn2 * 64 + mrow + lq] = mx0;
            pmax[wn2 * 64 + mrow + lq + 8] = mx1;
        }
        __syncthreads();
        const float nm0 = fmaxf(rmax0, fmaxf(pmax[mrow + lq], pmax[64 + mrow + lq]));
        const float nm1 = fmaxf(rmax1, fmaxf(pmax[mrow + lq + 8], pmax[64 + mrow + lq + 8]));
        const float alf0 = __expf(rmax0 - nm0);
        const float alf1 = __expf(rmax1 - nm1);
        rmax0 = nm0; rmax1 = nm1;

        float pv[4][4];
        float ls0 = 0.0f, ls1 = 0.0f;
#pragma unroll
        for (int ni = 0; ni < 4; ni++) {
            pv[ni][0] = __expf(sv[ni][0] - nm0);
            pv[ni][1] = __expf(sv[ni][1] - nm0);
            pv[ni][2] = __expf(sv[ni][2] - nm1);
            pv[ni][3] = __expf(sv[ni][3] - nm1);
            ls0 += pv[ni][0] + pv[ni][1];
            ls1 += pv[ni][2] + pv[ni][3];
        }
#pragma unroll
        for (int off = 1; off <= 2; off <<= 1) {
            ls0 += __shfl_xor_sync(0xffffffffu, ls0, off);
            ls1 += __shfl_xor_sync(0xffffffffu, ls1, off);
        }
        if (lr == 0) {
            psum[wn2 * 64 + mrow + lq] = ls0;
            psum[wn2 * 64 + mrow + lq + 8] = ls1;
        }
#pragma unroll
        for (int ni = 0; ni < 4; ni++) {
            const int c = ncol / 2 + ni * 4 + lr;
            const int a0 = (mrow + lq) * SQ2 + c;
            const int a1 = (mrow + lq + 8) * SQ2 + c;
            sKh[a0] = bfpack(pv[ni][0], pv[ni][1]);
            sKl[a0] = bfpack(bfres(pv[ni][0]), bfres(pv[ni][1]));
            sKh[a1] = bfpack(pv[ni][2], pv[ni][3]);
            sKl[a1] = bfpack(bfres(pv[ni][2]), bfres(pv[ni][3]));
        }
        __syncthreads();
        rsum0 = rsum0 * alf0 + psum[mrow + lq] + psum[64 + mrow + lq];
        rsum1 = rsum1 * alf1 + psum[mrow + lq + 8] + psum[64 + mrow + lq + 8];
#pragma unroll
        for (int ni = 0; ni < 4; ni++) {
            o[ni][0] *= alf0; o[ni][1] *= alf0;
            o[ni][2] *= alf1; o[ni][3] *= alf1;
        }

#pragma unroll
        for (int s = 0; s < 4; s++) {
            const int ks2 = s * 8;
            unsigned ph[4], pl[4];
            const int pb = (mrow + lq) * SQ2 + ks2 + lr;
            ph[0] = sKh[pb];  ph[1] = sKh[pb + 8 * SQ2];
            ph[2] = sKh[pb + 4]; ph[3] = sKh[pb + 8 * SQ2 + 4];
            pl[0] = sKl[pb];  pl[1] = sKl[pb + 8 * SQ2];
            pl[2] = sKl[pb + 4]; pl[3] = sKl[pb + 8 * SQ2 + 4];
#pragma unroll
            for (int ni = 0; ni < 4; ni++) {
                const int vb = (ncol + ni * 8 + lq) * SQ2 + ks2 + lr;
                unsigned bh[2] = {sVh[vb], sVh[vb + 4]};
                unsigned bl[2] = {sVl[vb], sVl[vb + 4]};
                mma_bf16(o[ni], ph, bh);
                mma_bf16(o[ni], ph, bl);
                mma_bf16(o[ni], pl, bh);
            }
        }
    }

#pragma unroll
    for (int ni = 0; ni < 4; ni++) {
        const int d = ncol + ni * 8 + lr * 2;
        *(float2*)&g_Op[sp][h][bm + mrow + lq][d] = make_float2(o[ni][0], o[ni][1]);
        *(float2*)&g_Op[sp][h][bm + mrow + lq + 8][d] = make_float2(o[ni][2], o[ni][3]);
    }
    if (lr == 0 && wn2 == 0) {
        g_mx[sp][h][bm + mrow + lq] = rmax0;
        g_ls[sp][h][bm + mrow + lq] = rsum0;
        g_mx[sp][h][bm + mrow + lq + 8] = rmax1;
        g_ls[sp][h][bm + mrow + lq + 8] = rsum1;
    }
}

// ---------------------------------------------------------------------------
// K4: merge split partials.
// ---------------------------------------------------------------------------
__global__ void __launch_bounds__(256) merge_k(float* __restrict__ out) {
    const int w = (blockIdx.x * 8) + (threadIdx.x >> 5);
    const int lane = threadIdx.x & 31;
    const int h = w >> 10;
    const int n = w & 1023;

    const float m0 = g_mx[0][h][n], m1 = g_mx[1][h][n];
    const float mM = fmaxf(m0, m1);
    const float e0 = __expf(m0 - mM), e1 = __expf(m1 - mM);
    const float inv = 1.0f / (g_ls[0][h][n] * e0 + g_ls[1][h][n] * e1);

    const float2 o0 = *(const float2*)&g_Op[0][h][n][lane * 2];
    const float2 o1 = *(const float2*)&g_Op[1][h][n][lane * 2];
    float2 r;
    r.x = (o0.x * e0 + o1.x * e1) * inv;
    r.y = (o0.y * e0 + o1.y * e1) * inv;
    *(float2*)(out + (size_t)n * DIM + h * HD + lane * 2) = r;
}

// ---------------------------------------------------------------------------
extern "C" void kernel_launch(void* const* d_in, const int* in_sizes, int n_in,
                              void* d_out, int out_size) {
    const float* x    = (const float*)d_in[0];
    const float* locs = (const float*)d_in[2];
    const float* Wqkv = (const float*)d_in[3];
    const float* Wloc = (const float*)d_in[4];
    const float* bloc = (const float*)d_in[5];
    float* out = (float*)d_out;

    cudaFuncSetAttribute(fused_attn, cudaFuncAttributeMaxDynamicSharedMemorySize,
                         ATTN_SMEM_U32 * 4);

    phase_tab<<<NN / 256, 256>>>(locs);
    qkv_gemm<<<QKV_BLOCKS, 256>>>(x, Wqkv);
    loc_bias<<<NN * NN / 256, 256>>>(locs, Wloc, bloc);
    fused_attn<<<(NN / BM) * HEADS * NSPLIT, 256, ATTN_SMEM_U32 * 4>>>();
    merge_k<<<HEADS * NN / 8, 256>>>(out);
}

// round 12
// speedup vs baseline: 1.2224x; 1.2224x over previous
#include <cuda_runtime.h>
#include <cuda_bf16.h>
#include <math.h>

#define NN 1024
#define DIM 512
#define QKVD 1536
#define HEADS 8
#define HD 64
#define BM 64
#define NSPLIT 4
#define MPART (NN / NSPLIT)   // 256 keys per split

#define QKV_MT 128
#define QKV_NT 64
#define QKV_BLOCKS ((NN / QKV_MT) * (QKVD / QKV_NT))   // 192

// Scratch (static device allocation only).
__device__ float g_qkv[NN * QKVD];
__device__ float g_S[(size_t)HEADS * NN * NN];
__device__ float g_Op[NSPLIT][HEADS][NN][HD];
__device__ float g_mx[NSPLIT][HEADS][NN];
__device__ float g_ls[NSPLIT][HEADS][NN];

// ---------------------------------------------------------------------------
// helpers
// ---------------------------------------------------------------------------
__device__ __forceinline__ unsigned cvt_tf32(float f) {
    unsigned u;
    asm("cvt.rna.tf32.f32 %0, %1;" : "=r"(u) : "f"(f));
    return u;
}
__device__ __forceinline__ void split_tf32(float f, unsigned& hi, unsigned& lo) {
    hi = cvt_tf32(f);
    lo = cvt_tf32(f - __uint_as_float(hi));
}
__device__ __forceinline__ void mma_tf32(float* c, const unsigned* a, const unsigned* b) {
    asm volatile(
        "mma.sync.aligned.m16n8k8.row.col.f32.tf32.tf32.f32 "
        "{%0,%1,%2,%3}, {%4,%5,%6,%7}, {%8,%9}, {%0,%1,%2,%3};"
        : "+f"(c[0]), "+f"(c[1]), "+f"(c[2]), "+f"(c[3])
        : "r"(a[0]), "r"(a[1]), "r"(a[2]), "r"(a[3]), "r"(b[0]), "r"(b[1]));
}
__device__ __forceinline__ void mma_bf16(float* c, const unsigned* a, const unsigned* b) {
    asm volatile(
        "mma.sync.aligned.m16n8k16.row.col.f32.bf16.bf16.f32 "
        "{%0,%1,%2,%3}, {%4,%5,%6,%7}, {%8,%9}, {%0,%1,%2,%3};"
        : "+f"(c[0]), "+f"(c[1]), "+f"(c[2]), "+f"(c[3])
        : "r"(a[0]), "r"(a[1]), "r"(a[2]), "r"(a[3]), "r"(b[0]), "r"(b[1]));
}
// pack two floats to bf16x2: lower half = first arg (even k), upper = second
__device__ __forceinline__ unsigned bfpack(float lo_e, float hi_e) {
    unsigned r;
    asm("cvt.rn.bf16x2.f32 %0, %1, %2;" : "=r"(r) : "f"(hi_e), "f"(lo_e));
    return r;
}
__device__ __forceinline__ float bfres(float f) {
    return f - __bfloat162float(__float2bfloat16(f));
}

// ---------------------------------------------------------------------------
// K1: tf32 QKV GEMM. 128x64 tile, 8 warps (4m x 2n).
// ---------------------------------------------------------------------------
__global__ void __launch_bounds__(256) qkv_gemm(const float* __restrict__ x,
                                                const float* __restrict__ W) {
    __shared__ float As[QKV_MT][20];
    __shared__ float Bs[QKV_NT][20];
    const int t = threadIdx.x;
    const int qb = blockIdx.x;
    const int bm = (qb % (NN / QKV_MT)) * QKV_MT;
    const int bn = (qb / (NN / QKV_MT)) * QKV_NT;
    const int w  = t >> 5, l = t & 31;
    const int wm = (w & 3) * 32;
    const int wn = (w >> 2) * 32;
    const int lq = l >> 2, lr = l & 3;

    const int arow = t >> 1;
    const int akc  = (t & 1) * 8;
    const float* Ap = x + (size_t)(bm + arow) * DIM + akc;
    const float* Bp = W + (size_t)(bn + (arow & 63)) * DIM + akc;

    float4 ra0 = *(const float4*)Ap;
    float4 ra1 = *(const float4*)(Ap + 4);
    float4 rb0 = make_float4(0, 0, 0, 0), rb1 = rb0;
    if (t < 128) { rb0 = *(const float4*)Bp; rb1 = *(const float4*)(Bp + 4); }

    float acc[2][4][4] = {};

    for (int kk = 0; kk < DIM; kk += 16) {
        __syncthreads();
        *(float4*)&As[arow][akc]     = ra0;
        *(float4*)&As[arow][akc + 4] = ra1;
        if (t < 128) {
            *(float4*)&Bs[arow & 63][akc]     = rb0;
            *(float4*)&Bs[arow & 63][akc + 4] = rb1;
        }
        __syncthreads();
        if (kk + 16 < DIM) {
            ra0 = *(const float4*)(Ap + kk + 16);
            ra1 = *(const float4*)(Ap + kk + 20);
            if (t < 128) {
                rb0 = *(const float4*)(Bp + kk + 16);
                rb1 = *(const float4*)(Bp + kk + 20);
            }
        }
#pragma unroll
        for (int ks = 0; ks < 16; ks += 8) {
            unsigned ahi[2][4], alo[2][4];
#pragma unroll
            for (int mi = 0; mi < 2; mi++) {
                const int r = wm + mi * 16;
                split_tf32(As[r + lq][ks + lr],          ahi[mi][0], alo[mi][0]);
                split_tf32(As[r + lq + 8][ks + lr],      ahi[mi][1], alo[mi][1]);
                split_tf32(As[r + lq][ks + lr + 4],      ahi[mi][2], alo[mi][2]);
                split_tf32(As[r + lq + 8][ks + lr + 4],  ahi[mi][3], alo[mi][3]);
            }
#pragma unroll
            for (int ni = 0; ni < 4; ni++) {
                unsigned bhi[2], blo[2];
                const int c = wn + ni * 8 + lq;
                split_tf32(Bs[c][ks + lr],     bhi[0], blo[0]);
                split_tf32(Bs[c][ks + lr + 4], bhi[1], blo[1]);
#pragma unroll
                for (int mi = 0; mi < 2; mi++) {
                    mma_tf32(acc[mi][ni], ahi[mi], bhi);
                    mma_tf32(acc[mi][ni], ahi[mi], blo);
                    mma_tf32(acc[mi][ni], alo[mi], bhi);
                }
            }
        }
    }
#pragma unroll
    for (int mi = 0; mi < 2; mi++)
#pragma unroll
        for (int ni = 0; ni < 4; ni++) {
            const int r = bm + wm + mi * 16 + lq;
            const int c = bn + wn + ni * 8 + lr * 2;
            *(float2*)&g_qkv[(size_t)r * QKVD + c] =
                make_float2(acc[mi][ni][0], acc[mi][ni][1]);
            *(float2*)&g_qkv[(size_t)(r + 8) * QKVD + c] =
                make_float2(acc[mi][ni][2], acc[mi][ni][3]);
        }
}

// ---------------------------------------------------------------------------
// K2: location bias (scalar, high occupancy — the R8 version; fastest so far).
// ---------------------------------------------------------------------------
__global__ void __launch_bounds__(256, 4) loc_bias(const float* __restrict__ locs,
                                                   const float* __restrict__ Wl,
                                                   const float* __restrict__ bl) {
    __shared__ float sW[8][64];
    __shared__ float sb[8];
    const int t = threadIdx.x;
    for (int i = t; i < 512; i += 256) sW[i >> 6][i & 63] = Wl[i];
    if (t < 8) sb[t] = bl[t];
    __syncthreads();

    const int lid = blockIdx.x;
    const int n = lid >> 2;
    const int m = (lid & 3) * 256 + t;

    const float4 bn = ((const float4*)locs)[n];
    const float4 bm = ((const float4*)locs)[m];
    const float wn = bn.z - bn.x + 1.0f, hn = bn.w - bn.y + 1.0f;
    const float wm = bm.z - bm.x + 1.0f, hm = bm.w - bm.y + 1.0f;
    const float cxn = 0.5f * (bn.x + bn.z), cyn = 0.5f * (bn.y + bn.w);
    const float cxm = 0.5f * (bm.x + bm.z), cym = 0.5f * (bm.y + bm.w);

    float pos[4];
    pos[0] = __logf(fmaxf(fabsf((cxn - cxm) / wn), 1e-3f));
    pos[1] = __logf(fmaxf(fabsf((cyn - cym) / hn), 1e-3f));
    pos[2] = __logf(wm / wn);
    pos[3] = __logf(hm / hn);

    const float invd[8] = {100.0f, 42.1696503f, 17.7827941f, 7.49894209f,
                           3.16227766f, 1.33352143f, 0.562341325f, 0.237137371f};

    float acc[8];
#pragma unroll
    for (int h = 0; h < 8; h++) acc[h] = sb[h];

#pragma unroll
    for (int g = 0; g < 4; g++) {
#pragma unroll
        for (int j = 0; j < 8; j++) {
            float sn, cs;
            __sincosf(pos[g] * invd[j], &sn, &cs);
#pragma unroll
            for (int h = 0; h < 8; h++)
                acc[h] = fmaf(sn, sW[h][g * 16 + j],
                              fmaf(cs, sW[h][g * 16 + 8 + j], acc[h]));
        }
    }
    const size_t base = (size_t)n * NN + m;
#pragma unroll
    for (int h = 0; h < 8; h++)
        g_S[(size_t)h * NN * NN + base] = __logf(fmaxf(acc[h], 0.0f) + 1e-6f);
}

// ---------------------------------------------------------------------------
// K3: split-KV flash attention, bf16x2 hi/lo 3-pass, mma m16n8k16.
// NSPLIT=4, 3 blocks/SM (regs capped at 85).
// ---------------------------------------------------------------------------
#define SQ2 36
#define A_Qh 0
#define A_Ql (64 * SQ2)
#define A_Kh (2 * 64 * SQ2)
#define A_Kl (3 * 64 * SQ2)
#define A_Vh (4 * 64 * SQ2)
#define A_Vl (5 * 64 * SQ2)
#define A_PM (6 * 64 * SQ2)
#define A_PS (A_PM + 128)
#define ATTN_SMEM_U32 (A_PS + 128)

__device__ __forceinline__ void load_split_row(const float* __restrict__ gp,
                                               unsigned* sh, unsigned* sl,
                                               int row, int quarter) {
    const float* p = gp + quarter * 16;
    float4 f0 = *(const float4*)p;
    float4 f1 = *(const float4*)(p + 4);
    float4 f2 = *(const float4*)(p + 8);
    float4 f3 = *(const float4*)(p + 12);
    const float f[16] = {f0.x, f0.y, f0.z, f0.w, f1.x, f1.y, f1.z, f1.w,
                         f2.x, f2.y, f2.z, f2.w, f3.x, f3.y, f3.z, f3.w};
    unsigned hi[8], lo[8];
#pragma unroll
    for (int j = 0; j < 8; j++) {
        hi[j] = bfpack(f[2 * j], f[2 * j + 1]);
        lo[j] = bfpack(bfres(f[2 * j]), bfres(f[2 * j + 1]));
    }
    const int a = row * SQ2 + quarter * 8;
    *(uint4*)&sh[a]     = make_uint4(hi[0], hi[1], hi[2], hi[3]);
    *(uint4*)&sh[a + 4] = make_uint4(hi[4], hi[5], hi[6], hi[7]);
    *(uint4*)&sl[a]     = make_uint4(lo[0], lo[1], lo[2], lo[3]);
    *(uint4*)&sl[a + 4] = make_uint4(lo[4], lo[5], lo[6], lo[7]);
}

__global__ void __launch_bounds__(256, 3) fused_attn() {
    extern __shared__ unsigned sm[];
    unsigned* sQh = sm + A_Qh;
    unsigned* sQl = sm + A_Ql;
    unsigned* sKh = sm + A_Kh;   // K in S phase; P in PV phase
    unsigned* sKl = sm + A_Kl;
    unsigned* sVh = sm + A_Vh;   // transposed: [d][mpair]
    unsigned* sVl = sm + A_Vl;
    float* pmax = (float*)(sm + A_PM);
    float* psum = (float*)(sm + A_PS);

    const int t = threadIdx.x;
    const int w = t >> 5, l = t & 31;
    const int lq = l >> 2, lr = l & 3;
    const int mrow = (w & 3) * 16;
    const int wn2  = w >> 2;
    const int ncol = wn2 * 32;

    const int h   = blockIdx.x & 7;
    const int qt  = (blockIdx.x >> 3) & 15;
    const int sp  = blockIdx.x >> 7;          // 0..3
    const int bm  = qt * BM;
    const int m0g = sp * MPART;

    const float* Qg = g_qkv + h * HD;
    const float* Kg = g_qkv + DIM + h * HD;
    const float* Vg = g_qkv + 2 * DIM + h * HD;
    const float* Bg = g_S + (size_t)h * NN * NN;

    {
        const int row = t >> 2;
        load_split_row(Qg + (size_t)(bm + row) * QKVD, sQh, sQl, row, t & 3);
    }

    float o[4][4] = {};
    float rmax0 = -INFINITY, rmax1 = -INFINITY;
    float rsum0 = 0.0f, rsum1 = 0.0f;

    for (int mt = 0; mt < MPART / 64; mt++) {
        const int mbase = m0g + mt * 64;
        __syncthreads();

        {
            const int row = t >> 2;
            load_split_row(Kg + (size_t)(mbase + row) * QKVD, sKh, sKl, row, t & 3);
        }
        {
            const int mp = t & 31;
            const int d0 = (t >> 5) * 8;
            const float* Vp0 = Vg + (size_t)(mbase + 2 * mp) * QKVD + d0;
            const float* Vp1 = Vp0 + QKVD;
            float4 a0 = *(const float4*)Vp0;
            float4 a1 = *(const float4*)(Vp0 + 4);
            float4 b0 = *(const float4*)Vp1;
            float4 b1 = *(const float4*)(Vp1 + 4);
            const float va[8] = {a0.x, a0.y, a0.z, a0.w, a1.x, a1.y, a1.z, a1.w};
            const float vb[8] = {b0.x, b0.y, b0.z, b0.w, b1.x, b1.y, b1.z, b1.w};
#pragma unroll
            for (int d = 0; d < 8; d++) {
                sVh[(d0 + d) * SQ2 + mp] = bfpack(va[d], vb[d]);
                sVl[(d0 + d) * SQ2 + mp] = bfpack(bfres(va[d]), bfres(vb[d]));
            }
        }
        float2 bia0[4], bia1[4];
#pragma unroll
        for (int ni = 0; ni < 4; ni++) {
            const size_t cb = (size_t)(bm + mrow + lq) * NN + mbase + ncol + ni * 8 + lr * 2;
            bia0[ni] = *(const float2*)(Bg + cb);
            bia1[ni] = *(const float2*)(Bg + cb + 8 * NN);
        }
        __syncthreads();

        float sc[4][4] = {};
#pragma unroll
        for (int s = 0; s < 4; s++) {
            const int ks2 = s * 8;
            unsigned ah[4], al_[4];
            const int ab = (mrow + lq) * SQ2 + ks2 + lr;
            ah[0] = sQh[ab];  ah[1] = sQh[ab + 8 * SQ2];
            ah[2] = sQh[ab + 4]; ah[3] = sQh[ab + 8 * SQ2 + 4];
            al_[0] = sQl[ab]; al_[1] = sQl[ab + 8 * SQ2];
            al_[2] = sQl[ab + 4]; al_[3] = sQl[ab + 8 * SQ2 + 4];
#pragma unroll
            for (int ni = 0; ni < 4; ni++) {
                const int bb = (ncol + ni * 8 + lq) * SQ2 + ks2 + lr;
                unsigned bh[2] = {sKh[bb], sKh[bb + 4]};
                unsigned bl[2] = {sKl[bb], sKl[bb + 4]};
                mma_bf16(sc[ni], ah, bh);
                mma_bf16(sc[ni], ah, bl);
                mma_bf16(sc[ni], al_, bh);
            }
        }

        float sv[4][4];
#pragma unroll
        for (int ni = 0; ni < 4; ni++) {
            sv[ni][0] = fmaf(0.125f, sc[ni][0], bia0[ni].x);
            sv[ni][1] = fmaf(0.125f, sc[ni][1], bia0[ni].y);
            sv[ni][2] = fmaf(0.125f, sc[ni][2], bia1[ni].x);
            sv[ni][3] = fmaf(0.125f, sc[ni][3], bia1[ni].y);
        }
        float mx0 = fmaxf(fmaxf(sv[0][0], sv[0][1]), fmaxf(sv[1][0], sv[1][1]));
        mx0 = fmaxf(mx0, fmaxf(fmaxf(sv[2][0], sv[2][1]), fmaxf(sv[3][0], sv[3][1])));
        float mx1 = fmaxf(fmaxf(sv[0][2], sv[0][3]), fmaxf(sv[1][2], sv[1][3]));
        mx1 = fmaxf(mx1, fmaxf(fmaxf(sv[2][2], sv[2][3]), fmaxf(sv[3][2], sv[3][3])));
#pragma unroll
        for (int off = 1; off <= 2; off <<= 1) {
            mx0 = fmaxf(mx0, __shfl_xor_sync(0xffffffffu, mx0, off));
            mx1 = fmaxf(mx1, __shfl_xor_sync(0xffffffffu, mx1, off));
        }
        if (lr == 0) {
            pmax[wn2 * 64 + mrow + lq] = mx0;
            pmax[wn2 * 64 + mrow + lq + 8] = mx1;
        }
        __syncthreads();
        const float nm0 = fmaxf(rmax0, fmaxf(pmax[mrow + lq], pmax[64 + mrow + lq]));
        const float nm1 = fmaxf(rmax1, fmaxf(pmax[mrow + lq + 8], pmax[64 + mrow + lq + 8]));
        const float alf0 = __expf(rmax0 - nm0);
        const float alf1 = __expf(rmax1 - nm1);
        rmax0 = nm0; rmax1 = nm1;

        float pv[4][4];
        float ls0 = 0.0f, ls1 = 0.0f;
#pragma unroll
        for (int ni = 0; ni < 4; ni++) {
            pv[ni][0] = __expf(sv[ni][0] - nm0);
            pv[ni][1] = __expf(sv[ni][1] - nm0);
            pv[ni][2] = __expf(sv[ni][2] - nm1);
            pv[ni][3] = __expf(sv[ni][3] - nm1);
            ls0 += pv[ni][0] + pv[ni][1];
            ls1 += pv[ni][2] + pv[ni][3];
        }
#pragma unroll
        for (int off = 1; off <= 2; off <<= 1) {
            ls0 += __shfl_xor_sync(0xffffffffu, ls0, off);
            ls1 += __shfl_xor_sync(0xffffffffu, ls1, off);
        }
        if (lr == 0) {
            psum[wn2 * 64 + mrow + lq] = ls0;
            psum[wn2 * 64 + mrow + lq + 8] = ls1;
        }
#pragma unroll
        for (int ni = 0; ni < 4; ni++) {
            const int c = ncol / 2 + ni * 4 + lr;
            const int a0 = (mrow + lq) * SQ2 + c;
            const int a1 = (mrow + lq + 8) * SQ2 + c;
            sKh[a0] = bfpack(pv[ni][0], pv[ni][1]);
            sKl[a0] = bfpack(bfres(pv[ni][0]), bfres(pv[ni][1]));
            sKh[a1] = bfpack(pv[ni][2], pv[ni][3]);
            sKl[a1] = bfpack(bfres(pv[ni][2]), bfres(pv[ni][3]));
        }
        __syncthreads();
        rsum0 = rsum0 * alf0 + psum[mrow + lq] + psum[64 + mrow + lq];
        rsum1 = rsum1 * alf1 + psum[mrow + lq + 8] + psum[64 + mrow + lq + 8];
#pragma unroll
        for (int ni = 0; ni < 4; ni++) {
            o[ni][0] *= alf0; o[ni][1] *= alf0;
            o[ni][2] *= alf1; o[ni][3] *= alf1;
        }

#pragma unroll
        for (int s = 0; s < 4; s++) {
            const int ks2 = s * 8;
            unsigned ph[4], pl[4];
            const int pb = (mrow + lq) * SQ2 + ks2 + lr;
            ph[0] = sKh[pb];  ph[1] = sKh[pb + 8 * SQ2];
            ph[2] = sKh[pb + 4]; ph[3] = sKh[pb + 8 * SQ2 + 4];
            pl[0] = sKl[pb];  pl[1] = sKl[pb + 8 * SQ2];
            pl[2] = sKl[pb + 4]; pl[3] = sKl[pb + 8 * SQ2 + 4];
#pragma unroll
            for (int ni = 0; ni < 4; ni++) {
                const int vb = (ncol + ni * 8 + lq) * SQ2 + ks2 + lr;
                unsigned bh[2] = {sVh[vb], sVh[vb + 4]};
                unsigned bl[2] = {sVl[vb], sVl[vb + 4]};
                mma_bf16(o[ni], ph, bh);
                mma_bf16(o[ni], ph, bl);
                mma_bf16(o[ni], pl, bh);
            }
        }
    }

#pragma unroll
    for (int ni = 0; ni < 4; ni++) {
        const int d = ncol + ni * 8 + lr * 2;
        *(float2*)&g_Op[sp][h][bm + mrow + lq][d] = make_float2(o[ni][0], o[ni][1]);
        *(float2*)&g_Op[sp][h][bm + mrow + lq + 8][d] = make_float2(o[ni][2], o[ni][3]);
    }
    if (lr == 0 && wn2 == 0) {
        g_mx[sp][h][bm + mrow + lq] = rmax0;
        g_ls[sp][h][bm + mrow + lq] = rsum0;
        g_mx[sp][h][bm + mrow + lq + 8] = rmax1;
        g_ls[sp][h][bm + mrow + lq + 8] = rsum1;
    }
}

// ---------------------------------------------------------------------------
// K4: merge NSPLIT partials.
// ---------------------------------------------------------------------------
__global__ void __launch_bounds__(256) merge_k(float* __restrict__ out) {
    const int w = (blockIdx.x * 8) + (threadIdx.x >> 5);
    const int lane = threadIdx.x & 31;
    const int h = w >> 10;
    const int n = w & 1023;

    float mM = -INFINITY;
#pragma unroll
    for (int s = 0; s < NSPLIT; s++) mM = fmaxf(mM, g_mx[s][h][n]);
    float e[NSPLIT];
    float denom = 0.0f;
#pragma unroll
    for (int s = 0; s < NSPLIT; s++) {
        e[s] = __expf(g_mx[s][h][n] - mM);
        denom += g_ls[s][h][n] * e[s];
    }
    const float inv = 1.0f / denom;

    float2 r = make_float2(0.0f, 0.0f);
#pragma unroll
    for (int s = 0; s < NSPLIT; s++) {
        const float2 os = *(const float2*)&g_Op[s][h][n][lane * 2];
        r.x += os.x * e[s];
        r.y += os.y * e[s];
    }
    r.x *= inv; r.y *= inv;
    *(float2*)(out + (size_t)n * DIM + h * HD + lane * 2) = r;
}

// ---------------------------------------------------------------------------
extern "C" void kernel_launch(void* const* d_in, const int* in_sizes, int n_in,
                              void* d_out, int out_size) {
    const float* x    = (const float*)d_in[0];
    const float* locs = (const float*)d_in[2];
    const float* Wqkv = (const float*)d_in[3];
    const float* Wloc = (const float*)d_in[4];
    const float* bloc = (const float*)d_in[5];
    float* out = (float*)d_out;

    cudaFuncSetAttribute(fused_attn, cudaFuncAttributeMaxDynamicSharedMemorySize,
                         ATTN_SMEM_U32 * 4);

    qkv_gemm<<<QKV_BLOCKS, 256>>>(x, Wqkv);
    loc_bias<<<NN * NN / 256, 256>>>(locs, Wloc, bloc);
    fused_attn<<<(NN / BM) * HEADS * NSPLIT, 256, ATTN_SMEM_U32 * 4>>>();
    merge_k<<<HEADS * NN / 8, 256>>>(out);
}

// round 13
// speedup vs baseline: 1.3471x; 1.1020x over previous
#include <cuda_runtime.h>
#include <cuda_bf16.h>
#include <math.h>

#define NN 1024
#define DIM 512
#define QKVD 1536
#define HEADS 8
#define HD 64
#define BM 64
#define NSPLIT 4
#define MPART (NN / NSPLIT)   // 256 keys per split

#define QKV_MT 128
#define QKV_NT 64
#define QKV_BLOCKS ((NN / QKV_MT) * (QKVD / QKV_NT))   // 192
#define LOC_BLOCKS (NN * NN / 256)                      // 4096

// Scratch (static device allocation only).
__device__ float g_qkv[NN * QKVD];
__device__ float g_S[(size_t)HEADS * NN * NN];
__device__ float g_Op[NSPLIT][HEADS][NN][HD];
__device__ float g_mx[NSPLIT][HEADS][NN];
__device__ float g_ls[NSPLIT][HEADS][NN];

// ---------------------------------------------------------------------------
// helpers
// ---------------------------------------------------------------------------
__device__ __forceinline__ unsigned cvt_tf32(float f) {
    unsigned u;
    asm("cvt.rna.tf32.f32 %0, %1;" : "=r"(u) : "f"(f));
    return u;
}
__device__ __forceinline__ void split_tf32(float f, unsigned& hi, unsigned& lo) {
    hi = cvt_tf32(f);
    lo = cvt_tf32(f - __uint_as_float(hi));
}
__device__ __forceinline__ void mma_tf32(float* c, const unsigned* a, const unsigned* b) {
    asm volatile(
        "mma.sync.aligned.m16n8k8.row.col.f32.tf32.tf32.f32 "
        "{%0,%1,%2,%3}, {%4,%5,%6,%7}, {%8,%9}, {%0,%1,%2,%3};"
        : "+f"(c[0]), "+f"(c[1]), "+f"(c[2]), "+f"(c[3])
        : "r"(a[0]), "r"(a[1]), "r"(a[2]), "r"(a[3]), "r"(b[0]), "r"(b[1]));
}
__device__ __forceinline__ void mma_bf16(float* c, const unsigned* a, const unsigned* b) {
    asm volatile(
        "mma.sync.aligned.m16n8k16.row.col.f32.bf16.bf16.f32 "
        "{%0,%1,%2,%3}, {%4,%5,%6,%7}, {%8,%9}, {%0,%1,%2,%3};"
        : "+f"(c[0]), "+f"(c[1]), "+f"(c[2]), "+f"(c[3])
        : "r"(a[0]), "r"(a[1]), "r"(a[2]), "r"(a[3]), "r"(b[0]), "r"(b[1]));
}
// pack two floats to bf16x2: lower half = first arg (even k), upper = second
__device__ __forceinline__ unsigned bfpack(float lo_e, float hi_e) {
    unsigned r;
    asm("cvt.rn.bf16x2.f32 %0, %1, %2;" : "=r"(r) : "f"(hi_e), "f"(lo_e));
    return r;
}
__device__ __forceinline__ float bfres(float f) {
    return f - __bfloat162float(__float2bfloat16(f));
}

// ---------------------------------------------------------------------------
// K1 (fused): blocks [0,192) = tf32 QKV GEMM tile; [192, 4288) = loc bias.
// __launch_bounds__(256,3): 85-reg cap -> loc branch keeps 3 blocks/SM while
// the 192 qkv blocks overlap underneath.
// ---------------------------------------------------------------------------
struct SmemQkv {
    float As[QKV_MT][20];
    float Bs[QKV_NT][20];
};
struct SmemLoc {
    float sW[8][64];
    float sb[8];
};

__global__ void __launch_bounds__(256, 3) fused_pre(const float* __restrict__ x,
                                                    const float* __restrict__ W,
                                                    const float* __restrict__ locs,
                                                    const float* __restrict__ Wl,
                                                    const float* __restrict__ bl) {
    __shared__ char smem_raw[sizeof(SmemQkv)];
    const int t = threadIdx.x;

    if (blockIdx.x < QKV_BLOCKS) {
        SmemQkv* s = (SmemQkv*)smem_raw;
        const int qb = blockIdx.x;
        const int bm = (qb % (NN / QKV_MT)) * QKV_MT;
        const int bn = (qb / (NN / QKV_MT)) * QKV_NT;
        const int w  = t >> 5, l = t & 31;
        const int wm = (w & 3) * 32;
        const int wn = (w >> 2) * 32;
        const int lq = l >> 2, lr = l & 3;

        const int arow = t >> 1;
        const int akc  = (t & 1) * 8;
        const float* Ap = x + (size_t)(bm + arow) * DIM + akc;
        const float* Bp = W + (size_t)(bn + (arow & 63)) * DIM + akc;

        float4 ra0 = *(const float4*)Ap;
        float4 ra1 = *(const float4*)(Ap + 4);
        float4 rb0 = make_float4(0, 0, 0, 0), rb1 = rb0;
        if (t < 128) { rb0 = *(const float4*)Bp; rb1 = *(const float4*)(Bp + 4); }

        float acc[2][4][4] = {};

        for (int kk = 0; kk < DIM; kk += 16) {
            __syncthreads();
            *(float4*)&s->As[arow][akc]     = ra0;
            *(float4*)&s->As[arow][akc + 4] = ra1;
            if (t < 128) {
                *(float4*)&s->Bs[arow & 63][akc]     = rb0;
                *(float4*)&s->Bs[arow & 63][akc + 4] = rb1;
            }
            __syncthreads();
            if (kk + 16 < DIM) {
                ra0 = *(const float4*)(Ap + kk + 16);
                ra1 = *(const float4*)(Ap + kk + 20);
                if (t < 128) {
                    rb0 = *(const float4*)(Bp + kk + 16);
                    rb1 = *(const float4*)(Bp + kk + 20);
                }
            }
#pragma unroll
            for (int ks = 0; ks < 16; ks += 8) {
                unsigned ahi[2][4], alo[2][4];
#pragma unroll
                for (int mi = 0; mi < 2; mi++) {
                    const int r = wm + mi * 16;
                    split_tf32(s->As[r + lq][ks + lr],          ahi[mi][0], alo[mi][0]);
                    split_tf32(s->As[r + lq + 8][ks + lr],      ahi[mi][1], alo[mi][1]);
                    split_tf32(s->As[r + lq][ks + lr + 4],      ahi[mi][2], alo[mi][2]);
                    split_tf32(s->As[r + lq + 8][ks + lr + 4],  ahi[mi][3], alo[mi][3]);
                }
#pragma unroll
                for (int ni = 0; ni < 4; ni++) {
                    unsigned bhi[2], blo[2];
                    const int c = wn + ni * 8 + lq;
                    split_tf32(s->Bs[c][ks + lr],     bhi[0], blo[0]);
                    split_tf32(s->Bs[c][ks + lr + 4], bhi[1], blo[1]);
#pragma unroll
                    for (int mi = 0; mi < 2; mi++) {
                        mma_tf32(acc[mi][ni], ahi[mi], bhi);
                        mma_tf32(acc[mi][ni], ahi[mi], blo);
                        mma_tf32(acc[mi][ni], alo[mi], bhi);
                    }
                }
            }
        }
#pragma unroll
        for (int mi = 0; mi < 2; mi++)
#pragma unroll
            for (int ni = 0; ni < 4; ni++) {
                const int r = bm + wm + mi * 16 + lq;
                const int c = bn + wn + ni * 8 + lr * 2;
                *(float2*)&g_qkv[(size_t)r * QKVD + c] =
                    make_float2(acc[mi][ni][0], acc[mi][ni][1]);
                *(float2*)&g_qkv[(size_t)(r + 8) * QKVD + c] =
                    make_float2(acc[mi][ni][2], acc[mi][ni][3]);
            }
    } else {
        SmemLoc* s = (SmemLoc*)smem_raw;
        for (int i = t; i < 512; i += 256) s->sW[i >> 6][i & 63] = Wl[i];
        if (t < 8) s->sb[t] = bl[t];
        __syncthreads();

        const int lid = blockIdx.x - QKV_BLOCKS;
        const int n = lid >> 2;
        const int m = (lid & 3) * 256 + t;

        const float4 bn = ((const float4*)locs)[n];
        const float4 bm = ((const float4*)locs)[m];
        const float wn = bn.z - bn.x + 1.0f, hn = bn.w - bn.y + 1.0f;
        const float wm = bm.z - bm.x + 1.0f, hm = bm.w - bm.y + 1.0f;
        const float cxn = 0.5f * (bn.x + bn.z), cyn = 0.5f * (bn.y + bn.w);
        const float cxm = 0.5f * (bm.x + bm.z), cym = 0.5f * (bm.y + bm.w);

        float pos[4];
        pos[0] = __logf(fmaxf(fabsf((cxn - cxm) / wn), 1e-3f));
        pos[1] = __logf(fmaxf(fabsf((cyn - cym) / hn), 1e-3f));
        pos[2] = __logf(wm / wn);
        pos[3] = __logf(hm / hn);

        const float invd[8] = {100.0f, 42.1696503f, 17.7827941f, 7.49894209f,
                               3.16227766f, 1.33352143f, 0.562341325f, 0.237137371f};

        float acc[8];
#pragma unroll
        for (int h = 0; h < 8; h++) acc[h] = s->sb[h];

#pragma unroll
        for (int g = 0; g < 4; g++) {
#pragma unroll
            for (int j = 0; j < 8; j++) {
                float sn, cs;
                __sincosf(pos[g] * invd[j], &sn, &cs);
#pragma unroll
                for (int h = 0; h < 8; h++)
                    acc[h] = fmaf(sn, s->sW[h][g * 16 + j],
                                  fmaf(cs, s->sW[h][g * 16 + 8 + j], acc[h]));
            }
        }
        const size_t base = (size_t)n * NN + m;
#pragma unroll
        for (int h = 0; h < 8; h++)
            g_S[(size_t)h * NN * NN + base] = __logf(fmaxf(acc[h], 0.0f) + 1e-6f);
    }
}

// ---------------------------------------------------------------------------
// K2: split-KV flash attention, bf16x2 hi/lo 3-pass, mma m16n8k16.
// NSPLIT=4, 3 blocks/SM.
// ---------------------------------------------------------------------------
#define SQ2 36
#define A_Qh 0
#define A_Ql (64 * SQ2)
#define A_Kh (2 * 64 * SQ2)
#define A_Kl (3 * 64 * SQ2)
#define A_Vh (4 * 64 * SQ2)
#define A_Vl (5 * 64 * SQ2)
#define A_PM (6 * 64 * SQ2)
#define A_PS (A_PM + 128)
#define ATTN_SMEM_U32 (A_PS + 128)

__device__ __forceinline__ void load_split_row(const float* __restrict__ gp,
                                               unsigned* sh, unsigned* sl,
                                               int row, int quarter) {
    const float* p = gp + quarter * 16;
    float4 f0 = *(const float4*)p;
    float4 f1 = *(const float4*)(p + 4);
    float4 f2 = *(const float4*)(p + 8);
    float4 f3 = *(const float4*)(p + 12);
    const float f[16] = {f0.x, f0.y, f0.z, f0.w, f1.x, f1.y, f1.z, f1.w,
                         f2.x, f2.y, f2.z, f2.w, f3.x, f3.y, f3.z, f3.w};
    unsigned hi[8], lo[8];
#pragma unroll
    for (int j = 0; j < 8; j++) {
        hi[j] = bfpack(f[2 * j], f[2 * j + 1]);
        lo[j] = bfpack(bfres(f[2 * j]), bfres(f[2 * j + 1]));
    }
    const int a = row * SQ2 + quarter * 8;
    *(uint4*)&sh[a]     = make_uint4(hi[0], hi[1], hi[2], hi[3]);
    *(uint4*)&sh[a + 4] = make_uint4(hi[4], hi[5], hi[6], hi[7]);
    *(uint4*)&sl[a]     = make_uint4(lo[0], lo[1], lo[2], lo[3]);
    *(uint4*)&sl[a + 4] = make_uint4(lo[4], lo[5], lo[6], lo[7]);
}

__global__ void __launch_bounds__(256, 3) fused_attn() {
    extern __shared__ unsigned sm[];
    unsigned* sQh = sm + A_Qh;
    unsigned* sQl = sm + A_Ql;
    unsigned* sKh = sm + A_Kh;   // K in S phase; P in PV phase
    unsigned* sKl = sm + A_Kl;
    unsigned* sVh = sm + A_Vh;   // transposed: [d][mpair]
    unsigned* sVl = sm + A_Vl;
    float* pmax = (float*)(sm + A_PM);
    float* psum = (float*)(sm + A_PS);

    const int t = threadIdx.x;
    const int w = t >> 5, l = t & 31;
    const int lq = l >> 2, lr = l & 3;
    const int mrow = (w & 3) * 16;
    const int wn2  = w >> 2;
    const int ncol = wn2 * 32;

    const int h   = blockIdx.x & 7;
    const int qt  = (blockIdx.x >> 3) & 15;
    const int sp  = blockIdx.x >> 7;          // 0..3
    const int bm  = qt * BM;
    const int m0g = sp * MPART;

    const float* Qg = g_qkv + h * HD;
    const float* Kg = g_qkv + DIM + h * HD;
    const float* Vg = g_qkv + 2 * DIM + h * HD;
    const float* Bg = g_S + (size_t)h * NN * NN;

    {
        const int row = t >> 2;
        load_split_row(Qg + (size_t)(bm + row) * QKVD, sQh, sQl, row, t & 3);
    }

    float o[4][4] = {};
    float rmax0 = -INFINITY, rmax1 = -INFINITY;
    float rsum0 = 0.0f, rsum1 = 0.0f;

    for (int mt = 0; mt < MPART / 64; mt++) {
        const int mbase = m0g + mt * 64;
        __syncthreads();

        {
            const int row = t >> 2;
            load_split_row(Kg + (size_t)(mbase + row) * QKVD, sKh, sKl, row, t & 3);
        }
        {
            const int mp = t & 31;
            const int d0 = (t >> 5) * 8;
            const float* Vp0 = Vg + (size_t)(mbase + 2 * mp) * QKVD + d0;
            const float* Vp1 = Vp0 + QKVD;
            float4 a0 = *(const float4*)Vp0;
            float4 a1 = *(const float4*)(Vp0 + 4);
            float4 b0 = *(const float4*)Vp1;
            float4 b1 = *(const float4*)(Vp1 + 4);
            const float va[8] = {a0.x, a0.y, a0.z, a0.w, a1.x, a1.y, a1.z, a1.w};
            const float vb[8] = {b0.x, b0.y, b0.z, b0.w, b1.x, b1.y, b1.z, b1.w};
#pragma unroll
            for (int d = 0; d < 8; d++) {
                sVh[(d0 + d) * SQ2 + mp] = bfpack(va[d], vb[d]);
                sVl[(d0 + d) * SQ2 + mp] = bfpack(bfres(va[d]), bfres(vb[d]));
            }
        }
        float2 bia0[4], bia1[4];
#pragma unroll
        for (int ni = 0; ni < 4; ni++) {
            const size_t cb = (size_t)(bm + mrow + lq) * NN + mbase + ncol + ni * 8 + lr * 2;
            bia0[ni] = *(const float2*)(Bg + cb);
            bia1[ni] = *(const float2*)(Bg + cb + 8 * NN);
        }
        __syncthreads();

        float sc[4][4] = {};
#pragma unroll
        for (int s = 0; s < 4; s++) {
            const int ks2 = s * 8;
            unsigned ah[4], al_[4];
            const int ab = (mrow + lq) * SQ2 + ks2 + lr;
            ah[0] = sQh[ab];  ah[1] = sQh[ab + 8 * SQ2];
            ah[2] = sQh[ab + 4]; ah[3] = sQh[ab + 8 * SQ2 + 4];
            al_[0] = sQl[ab]; al_[1] = sQl[ab + 8 * SQ2];
            al_[2] = sQl[ab + 4]; al_[3] = sQl[ab + 8 * SQ2 + 4];
#pragma unroll
            for (int ni = 0; ni < 4; ni++) {
                const int bb = (ncol + ni * 8 + lq) * SQ2 + ks2 + lr;
                unsigned bh[2] = {sKh[bb], sKh[bb + 4]};
                unsigned bl[2] = {sKl[bb], sKl[bb + 4]};
                mma_bf16(sc[ni], ah, bh);
                mma_bf16(sc[ni], ah, bl);
                mma_bf16(sc[ni], al_, bh);
            }
        }

        float sv[4][4];
#pragma unroll
        for (int ni = 0; ni < 4; ni++) {
            sv[ni][0] = fmaf(0.125f, sc[ni][0], bia0[ni].x);
            sv[ni][1] = fmaf(0.125f, sc[ni][1], bia0[ni].y);
            sv[ni][2] = fmaf(0.125f, sc[ni][2], bia1[ni].x);
            sv[ni][3] = fmaf(0.125f, sc[ni][3], bia1[ni].y);
        }
        float mx0 = fmaxf(fmaxf(sv[0][0], sv[0][1]), fmaxf(sv[1][0], sv[1][1]));
        mx0 = fmaxf(mx0, fmaxf(fmaxf(sv[2][0], sv[2][1]), fmaxf(sv[3][0], sv[3][1])));
        float mx1 = fmaxf(fmaxf(sv[0][2], sv[0][3]), fmaxf(sv[1][2], sv[1][3]));
        mx1 = fmaxf(mx1, fmaxf(fmaxf(sv[2][2], sv[2][3]), fmaxf(sv[3][2], sv[3][3])));
#pragma unroll
        for (int off = 1; off <= 2; off <<= 1) {
            mx0 = fmaxf(mx0, __shfl_xor_sync(0xffffffffu, mx0, off));
            mx1 = fmaxf(mx1, __shfl_xor_sync(0xffffffffu, mx1, off));
        }
        if (lr == 0) {
            pmax[wn2 * 64 + mrow + lq] = mx0;
            pmax[wn2 * 64 + mrow + lq + 8] = mx1;
        }
        __syncthreads();
        const float nm0 = fmaxf(rmax0, fmaxf(pmax[mrow + lq], pmax[64 + mrow + lq]));
        const float nm1 = fmaxf(rmax1, fmaxf(pmax[mrow + lq + 8], pmax[64 + mrow + lq + 8]));
        const float alf0 = __expf(rmax0 - nm0);
        const float alf1 = __expf(rmax1 - nm1);
        rmax0 = nm0; rmax1 = nm1;

        float pv[4][4];
        float ls0 = 0.0f, ls1 = 0.0f;
#pragma unroll
        for (int ni = 0; ni < 4; ni++) {
            pv[ni][0] = __expf(sv[ni][0] - nm0);
            pv[ni][1] = __expf(sv[ni][1] - nm0);
            pv[ni][2] = __expf(sv[ni][2] - nm1);
            pv[ni][3] = __expf(sv[ni][3] - nm1);
            ls0 += pv[ni][0] + pv[ni][1];
            ls1 += pv[ni][2] + pv[ni][3];
        }
#pragma unroll
        for (int off = 1; off <= 2; off <<= 1) {
            ls0 += __shfl_xor_sync(0xffffffffu, ls0, off);
            ls1 += __shfl_xor_sync(0xffffffffu, ls1, off);
        }
        if (lr == 0) {
            psum[wn2 * 64 + mrow + lq] = ls0;
            psum[wn2 * 64 + mrow + lq + 8] = ls1;
        }
#pragma unroll
        for (int ni = 0; ni < 4; ni++) {
            const int c = ncol / 2 + ni * 4 + lr;
            const int a0 = (mrow + lq) * SQ2 + c;
            const int a1 = (mrow + lq + 8) * SQ2 + c;
            sKh[a0] = bfpack(pv[ni][0], pv[ni][1]);
            sKl[a0] = bfpack(bfres(pv[ni][0]), bfres(pv[ni][1]));
            sKh[a1] = bfpack(pv[ni][2], pv[ni][3]);
            sKl[a1] = bfpack(bfres(pv[ni][2]), bfres(pv[ni][3]));
        }
        __syncthreads();
        rsum0 = rsum0 * alf0 + psum[mrow + lq] + psum[64 + mrow + lq];
        rsum1 = rsum1 * alf1 + psum[mrow + lq + 8] + psum[64 + mrow + lq + 8];
#pragma unroll
        for (int ni = 0; ni < 4; ni++) {
            o[ni][0] *= alf0; o[ni][1] *= alf0;
            o[ni][2] *= alf1; o[ni][3] *= alf1;
        }

#pragma unroll
        for (int s = 0; s < 4; s++) {
            const int ks2 = s * 8;
            unsigned ph[4], pl[4];
            const int pb = (mrow + lq) * SQ2 + ks2 + lr;
            ph[0] = sKh[pb];  ph[1] = sKh[pb + 8 * SQ2];
            ph[2] = sKh[pb + 4]; ph[3] = sKh[pb + 8 * SQ2 + 4];
            pl[0] = sKl[pb];  pl[1] = sKl[pb + 8 * SQ2];
            pl[2] = sKl[pb + 4]; pl[3] = sKl[pb + 8 * SQ2 + 4];
#pragma unroll
            for (int ni = 0; ni < 4; ni++) {
                const int vb = (ncol + ni * 8 + lq) * SQ2 + ks2 + lr;
                unsigned bh[2] = {sVh[vb], sVh[vb + 4]};
                unsigned bl[2] = {sVl[vb], sVl[vb + 4]};
                mma_bf16(o[ni], ph, bh);
                mma_bf16(o[ni], ph, bl);
                mma_bf16(o[ni], pl, bh);
            }
        }
    }

#pragma unroll
    for (int ni = 0; ni < 4; ni++) {
        const int d = ncol + ni * 8 + lr * 2;
        *(float2*)&g_Op[sp][h][bm + mrow + lq][d] = make_float2(o[ni][0], o[ni][1]);
        *(float2*)&g_Op[sp][h][bm + mrow + lq + 8][d] = make_float2(o[ni][2], o[ni][3]);
    }
    if (lr == 0 && wn2 == 0) {
        g_mx[sp][h][bm + mrow + lq] = rmax0;
        g_ls[sp][h][bm + mrow + lq] = rsum0;
        g_mx[sp][h][bm + mrow + lq + 8] = rmax1;
        g_ls[sp][h][bm + mrow + lq + 8] = rsum1;
    }
}

// ---------------------------------------------------------------------------
// K3: merge NSPLIT partials.
// ---------------------------------------------------------------------------
__global__ void __launch_bounds__(256) merge_k(float* __restrict__ out) {
    const int w = (blockIdx.x * 8) + (threadIdx.x >> 5);
    const int lane = threadIdx.x & 31;
    const int h = w >> 10;
    const int n = w & 1023;

    float mM = -INFINITY;
#pragma unroll
    for (int s = 0; s < NSPLIT; s++) mM = fmaxf(mM, g_mx[s][h][n]);
    float e[NSPLIT];
    float denom = 0.0f;
#pragma unroll
    for (int s = 0; s < NSPLIT; s++) {
        e[s] = __expf(g_mx[s][h][n] - mM);
        denom += g_ls[s][h][n] * e[s];
    }
    const float inv = 1.0f / denom;

    float2 r = make_float2(0.0f, 0.0f);
#pragma unroll
    for (int s = 0; s < NSPLIT; s++) {
        const float2 os = *(const float2*)&g_Op[s][h][n][lane * 2];
        r.x += os.x * e[s];
        r.y += os.y * e[s];
    }
    r.x *= inv; r.y *= inv;
    *(float2*)(out + (size_t)n * DIM + h * HD + lane * 2) = r;
}

// ---------------------------------------------------------------------------
extern "C" void kernel_launch(void* const* d_in, const int* in_sizes, int n_in,
                              void* d_out, int out_size) {
    const float* x    = (const float*)d_in[0];
    const float* locs = (const float*)d_in[2];
    const float* Wqkv = (const float*)d_in[3];
    const float* Wloc = (const float*)d_in[4];
    const float* bloc = (const float*)d_in[5];
    float* out = (float*)d_out;

    cudaFuncSetAttribute(fused_attn, cudaFuncAttributeMaxDynamicSharedMemorySize,
                         ATTN_SMEM_U32 * 4);

    fused_pre<<<QKV_BLOCKS + LOC_BLOCKS, 256>>>(x, Wqkv, locs, Wloc, bloc);
    fused_attn<<<(NN / BM) * HEADS * NSPLIT, 256, ATTN_SMEM_U32 * 4>>>();
    merge_k<<<HEADS * NN / 8, 256>>>(out);
}

// round 15
// speedup vs baseline: 1.4054x; 1.0433x over previous
#include <cuda_runtime.h>
#include <cuda_bf16.h>
#include <math.h>

#define NN 1024
#define DIM 512
#define QKVD 1536
#define HEADS 8
#define HD 64
#define BM 64
#define NSPLIT 4
#define MPART (NN / NSPLIT)   // 256 keys per split

#define QKV_MT 128
#define QKV_NT 64
#define QKV_BLOCKS ((NN / QKV_MT) * (QKVD / QKV_NT))   // 192
#define LOC_BLOCKS (NN * NN / 256)                      // 4096

// Scratch (static device allocation only).
__device__ float g_qkv[NN * QKVD];
__device__ float g_S[(size_t)HEADS * NN * NN];
__device__ float g_Op[NSPLIT][HEADS][NN][HD];
__device__ float g_mx[NSPLIT][HEADS][NN];
__device__ float g_ls[NSPLIT][HEADS][NN];

// ---------------------------------------------------------------------------
// helpers
// ---------------------------------------------------------------------------
__device__ __forceinline__ unsigned cvt_tf32(float f) {
    unsigned u;
    asm("cvt.rna.tf32.f32 %0, %1;" : "=r"(u) : "f"(f));
    return u;
}
__device__ __forceinline__ void split_tf32(float f, unsigned& hi, unsigned& lo) {
    hi = cvt_tf32(f);
    lo = cvt_tf32(f - __uint_as_float(hi));
}
__device__ __forceinline__ void mma_tf32(float* c, const unsigned* a, const unsigned* b) {
    asm volatile(
        "mma.sync.aligned.m16n8k8.row.col.f32.tf32.tf32.f32 "
        "{%0,%1,%2,%3}, {%4,%5,%6,%7}, {%8,%9}, {%0,%1,%2,%3};"
        : "+f"(c[0]), "+f"(c[1]), "+f"(c[2]), "+f"(c[3])
        : "r"(a[0]), "r"(a[1]), "r"(a[2]), "r"(a[3]), "r"(b[0]), "r"(b[1]));
}
__device__ __forceinline__ void mma_bf16(float* c, const unsigned* a, const unsigned* b) {
    asm volatile(
        "mma.sync.aligned.m16n8k16.row.col.f32.bf16.bf16.f32 "
        "{%0,%1,%2,%3}, {%4,%5,%6,%7}, {%8,%9}, {%0,%1,%2,%3};"
        : "+f"(c[0]), "+f"(c[1]), "+f"(c[2]), "+f"(c[3])
        : "r"(a[0]), "r"(a[1]), "r"(a[2]), "r"(a[3]), "r"(b[0]), "r"(b[1]));
}
// pack two floats to bf16x2: lower half = first arg (even k), upper = second
__device__ __forceinline__ unsigned bfpack(float lo_e, float hi_e) {
    unsigned r;
    asm("cvt.rn.bf16x2.f32 %0, %1, %2;" : "=r"(r) : "f"(hi_e), "f"(lo_e));
    return r;
}
__device__ __forceinline__ float bfres(float f) {
    return f - __bfloat162float(__float2bfloat16(f));
}
// f32x2 packed helpers (FFMA2 path — only reachable via PTX)
__device__ __forceinline__ unsigned long long pack2(float lo, float hi) {
    unsigned long long r;
    asm("mov.b64 %0, {%1, %2};" : "=l"(r) : "f"(lo), "f"(hi));
    return r;
}
__device__ __forceinline__ void unpack2(unsigned long long v, float& lo, float& hi) {
    asm("mov.b64 {%0, %1}, %2;" : "=f"(lo), "=f"(hi) : "l"(v));
}
__device__ __forceinline__ unsigned long long fma2(unsigned long long a,
                                                   unsigned long long b,
                                                   unsigned long long c) {
    unsigned long long d;
    asm("fma.rn.f32x2 %0, %1, %2, %3;" : "=l"(d) : "l"(a), "l"(b), "l"(c));
    return d;
}

// ---------------------------------------------------------------------------
// K1 (fused): blocks [0,192) = tf32 QKV GEMM tile; [192, 4288) = loc bias.
// Loc branch uses FFMA2 (f32x2) for the 8-head accumulation.
// ---------------------------------------------------------------------------
struct SmemQkv {
    float As[QKV_MT][20];
    float Bs[QKV_NT][20];
};
struct SmemLoc {
    unsigned long long sW2[64][4];  // [feat][head-pair] = (W[2hp][f], W[2hp+1][f])
    float sb[8];
};

__global__ void __launch_bounds__(256, 3) fused_pre(const float* __restrict__ x,
                                                    const float* __restrict__ W,
                                                    const float* __restrict__ locs,
                                                    const float* __restrict__ Wl,
                                                    const float* __restrict__ bl) {
    __shared__ char smem_raw[sizeof(SmemQkv) > sizeof(SmemLoc) ? sizeof(SmemQkv)
                                                               : sizeof(SmemLoc)];
    const int t = threadIdx.x;

    if (blockIdx.x < QKV_BLOCKS) {
        SmemQkv* s = (SmemQkv*)smem_raw;
        const int qb = blockIdx.x;
        const int bm = (qb % (NN / QKV_MT)) * QKV_MT;
        const int bn = (qb / (NN / QKV_MT)) * QKV_NT;
        const int w  = t >> 5, l = t & 31;
        const int wm = (w & 3) * 32;
        const int wn = (w >> 2) * 32;
        const int lq = l >> 2, lr = l & 3;

        const int arow = t >> 1;
        const int akc  = (t & 1) * 8;
        const float* Ap = x + (size_t)(bm + arow) * DIM + akc;
        const float* Bp = W + (size_t)(bn + (arow & 63)) * DIM + akc;

        float4 ra0 = *(const float4*)Ap;
        float4 ra1 = *(const float4*)(Ap + 4);
        float4 rb0 = make_float4(0, 0, 0, 0), rb1 = rb0;
        if (t < 128) { rb0 = *(const float4*)Bp; rb1 = *(const float4*)(Bp + 4); }

        float acc[2][4][4] = {};

        for (int kk = 0; kk < DIM; kk += 16) {
            __syncthreads();
            *(float4*)&s->As[arow][akc]     = ra0;
            *(float4*)&s->As[arow][akc + 4] = ra1;
            if (t < 128) {
                *(float4*)&s->Bs[arow & 63][akc]     = rb0;
                *(float4*)&s->Bs[arow & 63][akc + 4] = rb1;
            }
            __syncthreads();
            if (kk + 16 < DIM) {
                ra0 = *(const float4*)(Ap + kk + 16);
                ra1 = *(const float4*)(Ap + kk + 20);
                if (t < 128) {
                    rb0 = *(const float4*)(Bp + kk + 16);
                    rb1 = *(const float4*)(Bp + kk + 20);
                }
            }
#pragma unroll
            for (int ks = 0; ks < 16; ks += 8) {
                unsigned ahi[2][4], alo[2][4];
#pragma unroll
                for (int mi = 0; mi < 2; mi++) {
                    const int r = wm + mi * 16;
                    split_tf32(s->As[r + lq][ks + lr],          ahi[mi][0], alo[mi][0]);
                    split_tf32(s->As[r + lq + 8][ks + lr],      ahi[mi][1], alo[mi][1]);
                    split_tf32(s->As[r + lq][ks + lr + 4],      ahi[mi][2], alo[mi][2]);
                    split_tf32(s->As[r + lq + 8][ks + lr + 4],  ahi[mi][3], alo[mi][3]);
                }
#pragma unroll
                for (int ni = 0; ni < 4; ni++) {
                    unsigned bhi[2], blo[2];
                    const int c = wn + ni * 8 + lq;
                    split_tf32(s->Bs[c][ks + lr],     bhi[0], blo[0]);
                    split_tf32(s->Bs[c][ks + lr + 4], bhi[1], blo[1]);
#pragma unroll
                    for (int mi = 0; mi < 2; mi++) {
                        mma_tf32(acc[mi][ni], ahi[mi], bhi);
                        mma_tf32(acc[mi][ni], ahi[mi], blo);
                        mma_tf32(acc[mi][ni], alo[mi], bhi);
                    }
                }
            }
        }
#pragma unroll
        for (int mi = 0; mi < 2; mi++)
#pragma unroll
            for (int ni = 0; ni < 4; ni++) {
                const int r = bm + wm + mi * 16 + lq;
                const int c = bn + wn + ni * 8 + lr * 2;
                *(float2*)&g_qkv[(size_t)r * QKVD + c] =
                    make_float2(acc[mi][ni][0], acc[mi][ni][1]);
                *(float2*)&g_qkv[(size_t)(r + 8) * QKVD + c] =
                    make_float2(acc[mi][ni][2], acc[mi][ni][3]);
            }
    } else {
        SmemLoc* s = (SmemLoc*)smem_raw;
        // Build head-pair packed W: sW2[f][hp] = (W[2hp][f], W[2hp+1][f])
        {
            const int f = t >> 2, hp = t & 3;   // 256 threads = 64x4
            s->sW2[f][hp] = pack2(Wl[(2 * hp) * 64 + f], Wl[(2 * hp + 1) * 64 + f]);
        }
        if (t < 8) s->sb[t] = bl[t];
        __syncthreads();

        const int lid = blockIdx.x - QKV_BLOCKS;
        const int n = lid >> 2;
        const int m = (lid & 3) * 256 + t;

        const float4 bn = ((const float4*)locs)[n];
        const float4 bm = ((const float4*)locs)[m];
        const float wn = bn.z - bn.x + 1.0f, hn = bn.w - bn.y + 1.0f;
        const float wm = bm.z - bm.x + 1.0f, hm = bm.w - bm.y + 1.0f;
        const float cxn = 0.5f * (bn.x + bn.z), cyn = 0.5f * (bn.y + bn.w);
        const float cxm = 0.5f * (bm.x + bm.z), cym = 0.5f * (bm.y + bm.w);

        float pos[4];
        pos[0] = __logf(fmaxf(fabsf((cxn - cxm) / wn), 1e-3f));
        pos[1] = __logf(fmaxf(fabsf((cyn - cym) / hn), 1e-3f));
        pos[2] = __logf(wm / wn);
        pos[3] = __logf(hm / hn);

        const float invd[8] = {100.0f, 42.1696503f, 17.7827941f, 7.49894209f,
                               3.16227766f, 1.33352143f, 0.562341325f, 0.237137371f};

        unsigned long long acc2[4];
#pragma unroll
        for (int hp = 0; hp < 4; hp++) acc2[hp] = pack2(s->sb[2 * hp], s->sb[2 * hp + 1]);

#pragma unroll
        for (int g = 0; g < 4; g++) {
#pragma unroll
            for (int j = 0; j < 8; j++) {
                float sn, cs;
                __sincosf(pos[g] * invd[j], &sn, &cs);
                const unsigned long long ss = pack2(sn, sn);
                const unsigned long long cc = pack2(cs, cs);
                const unsigned long long* ws_ = s->sW2[g * 16 + j];
                const unsigned long long* wc_ = s->sW2[g * 16 + 8 + j];
#pragma unroll
                for (int hp = 0; hp < 4; hp++) {
                    acc2[hp] = fma2(ss, ws_[hp], acc2[hp]);
                    acc2[hp] = fma2(cc, wc_[hp], acc2[hp]);
                }
            }
        }
        const size_t base = (size_t)n * NN + m;
#pragma unroll
        for (int hp = 0; hp < 4; hp++) {
            float a0, a1;
            unpack2(acc2[hp], a0, a1);
            g_S[(size_t)(2 * hp) * NN * NN + base]     = __logf(fmaxf(a0, 0.0f) + 1e-6f);
            g_S[(size_t)(2 * hp + 1) * NN * NN + base] = __logf(fmaxf(a1, 0.0f) + 1e-6f);
        }
    }
}

// ---------------------------------------------------------------------------
// K2: split-KV flash attention, bf16x2 hi/lo 3-pass, mma m16n8k16.
// NSPLIT=4, 3 blocks/SM.
// ---------------------------------------------------------------------------
#define SQ2 36
#define A_Qh 0
#define A_Ql (64 * SQ2)
#define A_Kh (2 * 64 * SQ2)
#define A_Kl (3 * 64 * SQ2)
#define A_Vh (4 * 64 * SQ2)
#define A_Vl (5 * 64 * SQ2)
#define A_PM (6 * 64 * SQ2)
#define A_PS (A_PM + 128)
#define ATTN_SMEM_U32 (A_PS + 128)

__device__ __forceinline__ void load_split_row(const float* __restrict__ gp,
                                               unsigned* sh, unsigned* sl,
                                               int row, int quarter) {
    const float* p = gp + quarter * 16;
    float4 f0 = *(const float4*)p;
    float4 f1 = *(const float4*)(p + 4);
    float4 f2 = *(const float4*)(p + 8);
    float4 f3 = *(const float4*)(p + 12);
    const float f[16] = {f0.x, f0.y, f0.z, f0.w, f1.x, f1.y, f1.z, f1.w,
                         f2.x, f2.y, f2.z, f2.w, f3.x, f3.y, f3.z, f3.w};
    unsigned hi[8], lo[8];
#pragma unroll
    for (int j = 0; j < 8; j++) {
        hi[j] = bfpack(f[2 * j], f[2 * j + 1]);
        lo[j] = bfpack(bfres(f[2 * j]), bfres(f[2 * j + 1]));
    }
    const int a = row * SQ2 + quarter * 8;
    *(uint4*)&sh[a]     = make_uint4(hi[0], hi[1], hi[2], hi[3]);
    *(uint4*)&sh[a + 4] = make_uint4(hi[4], hi[5], hi[6], hi[7]);
    *(uint4*)&sl[a]     = make_uint4(lo[0], lo[1], lo[2], lo[3]);
    *(uint4*)&sl[a + 4] = make_uint4(lo[4], lo[5], lo[6], lo[7]);
}

__global__ void __launch_bounds__(256, 3) fused_attn() {
    extern __shared__ unsigned sm[];
    unsigned* sQh = sm + A_Qh;
    unsigned* sQl = sm + A_Ql;
    unsigned* sKh = sm + A_Kh;   // K in S phase; P in PV phase
    unsigned* sKl = sm + A_Kl;
    unsigned* sVh = sm + A_Vh;   // transposed: [d][mpair]
    unsigned* sVl = sm + A_Vl;
    float* pmax = (float*)(sm + A_PM);
    float* psum = (float*)(sm + A_PS);

    const int t = threadIdx.x;
    const int w = t >> 5, l = t & 31;
    const int lq = l >> 2, lr = l & 3;
    const int mrow = (w & 3) * 16;
    const int wn2  = w >> 2;
    const int ncol = wn2 * 32;

    const int h   = blockIdx.x & 7;
    const int qt  = (blockIdx.x >> 3) & 15;
    const int sp  = blockIdx.x >> 7;          // 0..3
    const int bm  = qt * BM;
    const int m0g = sp * MPART;

    const float* Qg = g_qkv + h * HD;
    const float* Kg = g_qkv + DIM + h * HD;
    const float* Vg = g_qkv + 2 * DIM + h * HD;
    const float* Bg = g_S + (size_t)h * NN * NN;

    {
        const int row = t >> 2;
        load_split_row(Qg + (size_t)(bm + row) * QKVD, sQh, sQl, row, t & 3);
    }

    float o[4][4] = {};
    float rmax0 = -INFINITY, rmax1 = -INFINITY;
    float rsum0 = 0.0f, rsum1 = 0.0f;

    for (int mt = 0; mt < MPART / 64; mt++) {
        const int mbase = m0g + mt * 64;
        __syncthreads();

        {
            const int row = t >> 2;
            load_split_row(Kg + (size_t)(mbase + row) * QKVD, sKh, sKl, row, t & 3);
        }
        {
            const int mp = t & 31;
            const int d0 = (t >> 5) * 8;
            const float* Vp0 = Vg + (size_t)(mbase + 2 * mp) * QKVD + d0;
            const float* Vp1 = Vp0 + QKVD;
            float4 a0 = *(const float4*)Vp0;
            float4 a1 = *(const float4*)(Vp0 + 4);
            float4 b0 = *(const float4*)Vp1;
            float4 b1 = *(const float4*)(Vp1 + 4);
            const float va[8] = {a0.x, a0.y, a0.z, a0.w, a1.x, a1.y, a1.z, a1.w};
            const float vb[8] = {b0.x, b0.y, b0.z, b0.w, b1.x, b1.y, b1.z, b1.w};
#pragma unroll
            for (int d = 0; d < 8; d++) {
                sVh[(d0 + d) * SQ2 + mp] = bfpack(va[d], vb[d]);
                sVl[(d0 + d) * SQ2 + mp] = bfpack(bfres(va[d]), bfres(vb[d]));
            }
        }
        float2 bia0[4], bia1[4];
#pragma unroll
        for (int ni = 0; ni < 4; ni++) {
            const size_t cb = (size_t)(bm + mrow + lq) * NN + mbase + ncol + ni * 8 + lr * 2;
            bia0[ni] = *(const float2*)(Bg + cb);
            bia1[ni] = *(const float2*)(Bg + cb + 8 * NN);
        }
        __syncthreads();

        float sc[4][4] = {};
#pragma unroll
        for (int s = 0; s < 4; s++) {
            const int ks2 = s * 8;
            unsigned ah[4], al_[4];
            const int ab = (mrow + lq) * SQ2 + ks2 + lr;
            ah[0] = sQh[ab];  ah[1] = sQh[ab + 8 * SQ2];
            ah[2] = sQh[ab + 4]; ah[3] = sQh[ab + 8 * SQ2 + 4];
            al_[0] = sQl[ab]; al_[1] = sQl[ab + 8 * SQ2];
            al_[2] = sQl[ab + 4]; al_[3] = sQl[ab + 8 * SQ2 + 4];
#pragma unroll
            for (int ni = 0; ni < 4; ni++) {
                const int bb = (ncol + ni * 8 + lq) * SQ2 + ks2 + lr;
                unsigned bh[2] = {sKh[bb], sKh[bb + 4]};
                unsigned bl[2] = {sKl[bb], sKl[bb + 4]};
                mma_bf16(sc[ni], ah, bh);
                mma_bf16(sc[ni], ah, bl);
                mma_bf16(sc[ni], al_, bh);
            }
        }

        float sv[4][4];
#pragma unroll
        for (int ni = 0; ni < 4; ni++) {
            sv[ni][0] = fmaf(0.125f, sc[ni][0], bia0[ni].x);
            sv[ni][1] = fmaf(0.125f, sc[ni][1], bia0[ni].y);
            sv[ni][2] = fmaf(0.125f, sc[ni][2], bia1[ni].x);
            sv[ni][3] = fmaf(0.125f, sc[ni][3], bia1[ni].y);
        }
        float mx0 = fmaxf(fmaxf(sv[0][0], sv[0][1]), fmaxf(sv[1][0], sv[1][1]));
        mx0 = fmaxf(mx0, fmaxf(fmaxf(sv[2][0], sv[2][1]), fmaxf(sv[3][0], sv[3][1])));
        float mx1 = fmaxf(fmaxf(sv[0][2], sv[0][3]), fmaxf(sv[1][2], sv[1][3]));
        mx1 = fmaxf(mx1, fmaxf(fmaxf(sv[2][2], sv[2][3]), fmaxf(sv[3][2], sv[3][3])));
#pragma unroll
        for (int off = 1; off <= 2; off <<= 1) {
            mx0 = fmaxf(mx0, __shfl_xor_sync(0xffffffffu, mx0, off));
            mx1 = fmaxf(mx1, __shfl_xor_sync(0xffffffffu, mx1, off));
        }
        if (lr == 0) {
            pmax[wn2 * 64 + mrow + lq] = mx0;
            pmax[wn2 * 64 + mrow + lq + 8] = mx1;
        }
        __syncthreads();
        const float nm0 = fmaxf(rmax0, fmaxf(pmax[mrow + lq], pmax[64 + mrow + lq]));
        const float nm1 = fmaxf(rmax1, fmaxf(pmax[mrow + lq + 8], pmax[64 + mrow + lq + 8]));
        const float alf0 = __expf(rmax0 - nm0);
        const float alf1 = __expf(rmax1 - nm1);
        rmax0 = nm0; rmax1 = nm1;

        float pv[4][4];
        float ls0 = 0.0f, ls1 = 0.0f;
#pragma unroll
        for (int ni = 0; ni < 4; ni++) {
            pv[ni][0] = __expf(sv[ni][0] - nm0);
            pv[ni][1] = __expf(sv[ni][1] - nm0);
            pv[ni][2] = __expf(sv[ni][2] - nm1);
            pv[ni][3] = __expf(sv[ni][3] - nm1);
            ls0 += pv[ni][0] + pv[ni][1];
            ls1 += pv[ni][2] + pv[ni][3];
        }
#pragma unroll
        for (int off = 1; off <= 2; off <<= 1) {
            ls0 += __shfl_xor_sync(0xffffffffu, ls0, off);
            ls1 += __shfl_xor_sync(0xffffffffu, ls1, off);
        }
        if (lr == 0) {
            psum[wn2 * 64 + mrow + lq] = ls0;
            psum[wn2 * 64 + mrow + lq + 8] = ls1;
        }
#pragma unroll
        for (int ni = 0; ni < 4; ni++) {
            const int c = ncol / 2 + ni * 4 + lr;
            const int a0 = (mrow + lq) * SQ2 + c;
            const int a1 = (mrow + lq + 8) * SQ2 + c;
            sKh[a0] = bfpack(pv[ni][0], pv[ni][1]);
            sKl[a0] = bfpack(bfres(pv[ni][0]), bfres(pv[ni][1]));
            sKh[a1] = bfpack(pv[ni][2], pv[ni][3]);
            sKl[a1] = bfpack(bfres(pv[ni][2]), bfres(pv[ni][3]));
        }
        __syncthreads();
        rsum0 = rsum0 * alf0 + psum[mrow + lq] + psum[64 + mrow + lq];
        rsum1 = rsum1 * alf1 + psum[mrow + lq + 8] + psum[64 + mrow + lq + 8];
#pragma unroll
        for (int ni = 0; ni < 4; ni++) {
            o[ni][0] *= alf0; o[ni][1] *= alf0;
            o[ni][2] *= alf1; o[ni][3] *= alf1;
        }

#pragma unroll
        for (int s = 0; s < 4; s++) {
            const int ks2 = s * 8;
            unsigned ph[4], pl[4];
            const int pb = (mrow + lq) * SQ2 + ks2 + lr;
            ph[0] = sKh[pb];  ph[1] = sKh[pb + 8 * SQ2];
            ph[2] = sKh[pb + 4]; ph[3] = sKh[pb + 8 * SQ2 + 4];
            pl[0] = sKl[pb];  pl[1] = sKl[pb + 8 * SQ2];
            pl[2] = sKl[pb + 4]; pl[3] = sKl[pb + 8 * SQ2 + 4];
#pragma unroll
            for (int ni = 0; ni < 4; ni++) {
                const int vb = (ncol + ni * 8 + lq) * SQ2 + ks2 + lr;
                unsigned bh[2] = {sVh[vb], sVh[vb + 4]};
                unsigned bl[2] = {sVl[vb], sVl[vb + 4]};
                mma_bf16(o[ni], ph, bh);
                mma_bf16(o[ni], ph, bl);
                mma_bf16(o[ni], pl, bh);
            }
        }
    }

#pragma unroll
    for (int ni = 0; ni < 4; ni++) {
        const int d = ncol + ni * 8 + lr * 2;
        *(float2*)&g_Op[sp][h][bm + mrow + lq][d] = make_float2(o[ni][0], o[ni][1]);
        *(float2*)&g_Op[sp][h][bm + mrow + lq + 8][d] = make_float2(o[ni][2], o[ni][3]);
    }
    if (lr == 0 && wn2 == 0) {
        g_mx[sp][h][bm + mrow + lq] = rmax0;
        g_ls[sp][h][bm + mrow + lq] = rsum0;
        g_mx[sp][h][bm + mrow + lq + 8] = rmax1;
        g_ls[sp][h][bm + mrow + lq + 8] = rsum1;
    }
}

// ---------------------------------------------------------------------------
// K3: merge NSPLIT partials.
// ---------------------------------------------------------------------------
__global__ void __launch_bounds__(256) merge_k(float* __restrict__ out) {
    const int w = (blockIdx.x * 8) + (threadIdx.x >> 5);
    const int lane = threadIdx.x & 31;
    const int h = w >> 10;
    const int n = w & 1023;

    float mM = -INFINITY;
#pragma unroll
    for (int s = 0; s < NSPLIT; s++) mM = fmaxf(mM, g_mx[s][h][n]);
    float e[NSPLIT];
    float denom = 0.0f;
#pragma unroll
    for (int s = 0; s < NSPLIT; s++) {
        e[s] = __expf(g_mx[s][h][n] - mM);
        denom += g_ls[s][h][n] * e[s];
    }
    const float inv = 1.0f / denom;

    float2 r = make_float2(0.0f, 0.0f);
#pragma unroll
    for (int s = 0; s < NSPLIT; s++) {
        const float2 os = *(const float2*)&g_Op[s][h][n][lane * 2];
        r.x += os.x * e[s];
        r.y += os.y * e[s];
    }
    r.x *= inv; r.y *= inv;
    *(float2*)(out + (size_t)n * DIM + h * HD + lane * 2) = r;
}

// ---------------------------------------------------------------------------
extern "C" void kernel_launch(void* const* d_in, const int* in_sizes, int n_in,
                              void* d_out, int out_size) {
    const float* x    = (const float*)d_in[0];
    const float* locs = (const float*)d_in[2];
    const float* Wqkv = (const float*)d_in[3];
    const float* Wloc = (const float*)d_in[4];
    const float* bloc = (const float*)d_in[5];
    float* out = (float*)d_out;

    cudaFuncSetAttribute(fused_attn, cudaFuncAttributeMaxDynamicSharedMemorySize,
                         ATTN_SMEM_U32 * 4);

    fused_pre<<<QKV_BLOCKS + LOC_BLOCKS, 256>>>(x, Wqkv, locs, Wloc, bloc);
    fused_attn<<<(NN / BM) * HEADS * NSPLIT, 256, ATTN_SMEM_U32 * 4>>>();
    merge_k<<<HEADS * NN / 8, 256>>>(out);
}

// round 16
// speedup vs baseline: 1.4291x; 1.0168x over previous
#include <cuda_runtime.h>
#include <cuda_bf16.h>
#include <math.h>

#define NN 1024
#define DIM 512
#define QKVD 1536
#define HEADS 8
#define HD 64
#define BM 64
#define NSPLIT 4
#define MPART (NN / NSPLIT)   // 256 keys per split

#define QKV_MT 128
#define QKV_NT 64
#define QKV_BLOCKS ((NN / QKV_MT) * (QKVD / QKV_NT))   // 192
#define LOC_BLOCKS (NN * NN / 256)                      // 4096

// Scratch (static device allocation only).
__device__ float g_qkv[NN * QKVD];
__device__ float g_S[(size_t)HEADS * NN * NN];   // LINEAR bias: relu(.)+1e-6
__device__ float g_Op[NSPLIT][HEADS][NN][HD];
__device__ float g_ls[NSPLIT][HEADS][NN];

// ---------------------------------------------------------------------------
// helpers
// ---------------------------------------------------------------------------
__device__ __forceinline__ unsigned cvt_tf32(float f) {
    unsigned u;
    asm("cvt.rna.tf32.f32 %0, %1;" : "=r"(u) : "f"(f));
    return u;
}
__device__ __forceinline__ void split_tf32(float f, unsigned& hi, unsigned& lo) {
    hi = cvt_tf32(f);
    lo = cvt_tf32(f - __uint_as_float(hi));
}
__device__ __forceinline__ void mma_tf32(float* c, const unsigned* a, const unsigned* b) {
    asm volatile(
        "mma.sync.aligned.m16n8k8.row.col.f32.tf32.tf32.f32 "
        "{%0,%1,%2,%3}, {%4,%5,%6,%7}, {%8,%9}, {%0,%1,%2,%3};"
        : "+f"(c[0]), "+f"(c[1]), "+f"(c[2]), "+f"(c[3])
        : "r"(a[0]), "r"(a[1]), "r"(a[2]), "r"(a[3]), "r"(b[0]), "r"(b[1]));
}
__device__ __forceinline__ void mma_bf16(float* c, const unsigned* a, const unsigned* b) {
    asm volatile(
        "mma.sync.aligned.m16n8k16.row.col.f32.bf16.bf16.f32 "
        "{%0,%1,%2,%3}, {%4,%5,%6,%7}, {%8,%9}, {%0,%1,%2,%3};"
        : "+f"(c[0]), "+f"(c[1]), "+f"(c[2]), "+f"(c[3])
        : "r"(a[0]), "r"(a[1]), "r"(a[2]), "r"(a[3]), "r"(b[0]), "r"(b[1]));
}
__device__ __forceinline__ unsigned bfpack(float lo_e, float hi_e) {
    unsigned r;
    asm("cvt.rn.bf16x2.f32 %0, %1, %2;" : "=r"(r) : "f"(hi_e), "f"(lo_e));
    return r;
}
__device__ __forceinline__ float bfres(float f) {
    return f - __bfloat162float(__float2bfloat16(f));
}
__device__ __forceinline__ unsigned long long pack2(float lo, float hi) {
    unsigned long long r;
    asm("mov.b64 %0, {%1, %2};" : "=l"(r) : "f"(lo), "f"(hi));
    return r;
}
__device__ __forceinline__ void unpack2(unsigned long long v, float& lo, float& hi) {
    asm("mov.b64 {%0, %1}, %2;" : "=f"(lo), "=f"(hi) : "l"(v));
}
__device__ __forceinline__ unsigned long long fma2(unsigned long long a,
                                                   unsigned long long b,
                                                   unsigned long long c) {
    unsigned long long d;
    asm("fma.rn.f32x2 %0, %1, %2, %3;" : "=l"(d) : "l"(a), "l"(b), "l"(c));
    return d;
}

// ---------------------------------------------------------------------------
// K1 (fused): blocks [0,192) = tf32 QKV GEMM tile; [192, 4288) = loc bias.
// ---------------------------------------------------------------------------
struct SmemQkv {
    float As[QKV_MT][20];
    float Bs[QKV_NT][20];
};
struct SmemLoc {
    unsigned long long sW2[64][4];  // [feat][head-pair]; rows 32B-aligned
    float sb[8];
};

__global__ void __launch_bounds__(256, 3) fused_pre(const float* __restrict__ x,
                                                    const float* __restrict__ W,
                                                    const float* __restrict__ locs,
                                                    const float* __restrict__ Wl,
                                                    const float* __restrict__ bl) {
    __shared__ char smem_raw[sizeof(SmemQkv) > sizeof(SmemLoc) ? sizeof(SmemQkv)
                                                               : sizeof(SmemLoc)];
    const int t = threadIdx.x;

    if (blockIdx.x < QKV_BLOCKS) {
        SmemQkv* s = (SmemQkv*)smem_raw;
        const int qb = blockIdx.x;
        const int bm = (qb % (NN / QKV_MT)) * QKV_MT;
        const int bn = (qb / (NN / QKV_MT)) * QKV_NT;
        const int w  = t >> 5, l = t & 31;
        const int wm = (w & 3) * 32;
        const int wn = (w >> 2) * 32;
        const int lq = l >> 2, lr = l & 3;

        const int arow = t >> 1;
        const int akc  = (t & 1) * 8;
        const float* Ap = x + (size_t)(bm + arow) * DIM + akc;
        const float* Bp = W + (size_t)(bn + (arow & 63)) * DIM + akc;

        float4 ra0 = *(const float4*)Ap;
        float4 ra1 = *(const float4*)(Ap + 4);
        float4 rb0 = make_float4(0, 0, 0, 0), rb1 = rb0;
        if (t < 128) { rb0 = *(const float4*)Bp; rb1 = *(const float4*)(Bp + 4); }

        float acc[2][4][4] = {};

        for (int kk = 0; kk < DIM; kk += 16) {
            __syncthreads();
            *(float4*)&s->As[arow][akc]     = ra0;
            *(float4*)&s->As[arow][akc + 4] = ra1;
            if (t < 128) {
                *(float4*)&s->Bs[arow & 63][akc]     = rb0;
                *(float4*)&s->Bs[arow & 63][akc + 4] = rb1;
            }
            __syncthreads();
            if (kk + 16 < DIM) {
                ra0 = *(const float4*)(Ap + kk + 16);
                ra1 = *(const float4*)(Ap + kk + 20);
                if (t < 128) {
                    rb0 = *(const float4*)(Bp + kk + 16);
                    rb1 = *(const float4*)(Bp + kk + 20);
                }
            }
#pragma unroll
            for (int ks = 0; ks < 16; ks += 8) {
                unsigned ahi[2][4], alo[2][4];
#pragma unroll
                for (int mi = 0; mi < 2; mi++) {
                    const int r = wm + mi * 16;
                    split_tf32(s->As[r + lq][ks + lr],          ahi[mi][0], alo[mi][0]);
                    split_tf32(s->As[r + lq + 8][ks + lr],      ahi[mi][1], alo[mi][1]);
                    split_tf32(s->As[r + lq][ks + lr + 4],      ahi[mi][2], alo[mi][2]);
                    split_tf32(s->As[r + lq + 8][ks + lr + 4],  ahi[mi][3], alo[mi][3]);
                }
#pragma unroll
                for (int ni = 0; ni < 4; ni++) {
                    unsigned bhi[2], blo[2];
                    const int c = wn + ni * 8 + lq;
                    split_tf32(s->Bs[c][ks + lr],     bhi[0], blo[0]);
                    split_tf32(s->Bs[c][ks + lr + 4], bhi[1], blo[1]);
#pragma unroll
                    for (int mi = 0; mi < 2; mi++) {
                        mma_tf32(acc[mi][ni], ahi[mi], bhi);
                        mma_tf32(acc[mi][ni], ahi[mi], blo);
                        mma_tf32(acc[mi][ni], alo[mi], bhi);
                    }
                }
            }
        }
#pragma unroll
        for (int mi = 0; mi < 2; mi++)
#pragma unroll
            for (int ni = 0; ni < 4; ni++) {
                const int r = bm + wm + mi * 16 + lq;
                const int c = bn + wn + ni * 8 + lr * 2;
                *(float2*)&g_qkv[(size_t)r * QKVD + c] =
                    make_float2(acc[mi][ni][0], acc[mi][ni][1]);
                *(float2*)&g_qkv[(size_t)(r + 8) * QKVD + c] =
                    make_float2(acc[mi][ni][2], acc[mi][ni][3]);
            }
    } else {
        SmemLoc* s = (SmemLoc*)smem_raw;
        {
            const int f = t >> 2, hp = t & 3;
            s->sW2[f][hp] = pack2(Wl[(2 * hp) * 64 + f], Wl[(2 * hp + 1) * 64 + f]);
        }
        if (t < 8) s->sb[t] = bl[t];
        __syncthreads();

        const int lid = blockIdx.x - QKV_BLOCKS;
        const int n = lid >> 2;
        const int m = (lid & 3) * 256 + t;

        const float4 bn = ((const float4*)locs)[n];
        const float4 bm = ((const float4*)locs)[m];
        const float wn = bn.z - bn.x + 1.0f, hn = bn.w - bn.y + 1.0f;
        const float wm = bm.z - bm.x + 1.0f, hm = bm.w - bm.y + 1.0f;
        const float cxn = 0.5f * (bn.x + bn.z), cyn = 0.5f * (bn.y + bn.w);
        const float cxm = 0.5f * (bm.x + bm.z), cym = 0.5f * (bm.y + bm.w);

        float pos[4];
        pos[0] = __logf(fmaxf(fabsf((cxn - cxm) / wn), 1e-3f));
        pos[1] = __logf(fmaxf(fabsf((cyn - cym) / hn), 1e-3f));
        pos[2] = __logf(wm / wn);
        pos[3] = __logf(hm / hn);

        const float invd[8] = {100.0f, 42.1696503f, 17.7827941f, 7.49894209f,
                               3.16227766f, 1.33352143f, 0.562341325f, 0.237137371f};

        unsigned long long acc2[4];
#pragma unroll
        for (int hp = 0; hp < 4; hp++) acc2[hp] = pack2(s->sb[2 * hp], s->sb[2 * hp + 1]);

#pragma unroll
        for (int g = 0; g < 4; g++) {
#pragma unroll
            for (int j = 0; j < 8; j++) {
                float sn, cs;
                __sincosf(pos[g] * invd[j], &sn, &cs);
                const unsigned long long ss = pack2(sn, sn);
                const unsigned long long cc = pack2(cs, cs);
                const ulonglong2* wsp = (const ulonglong2*)s->sW2[g * 16 + j];
                const ulonglong2* wcp = (const ulonglong2*)s->sW2[g * 16 + 8 + j];
                ulonglong2 w01 = wsp[0], w23 = wsp[1];
                ulonglong2 c01 = wcp[0], c23 = wcp[1];
                acc2[0] = fma2(ss, w01.x, acc2[0]);
                acc2[1] = fma2(ss, w01.y, acc2[1]);
                acc2[2] = fma2(ss, w23.x, acc2[2]);
                acc2[3] = fma2(ss, w23.y, acc2[3]);
                acc2[0] = fma2(cc, c01.x, acc2[0]);
                acc2[1] = fma2(cc, c01.y, acc2[1]);
                acc2[2] = fma2(cc, c23.x, acc2[2]);
                acc2[3] = fma2(cc, c23.y, acc2[3]);
            }
        }
        const size_t base = (size_t)n * NN + m;
#pragma unroll
        for (int hp = 0; hp < 4; hp++) {
            float a0, a1;
            unpack2(acc2[hp], a0, a1);
            g_S[(size_t)(2 * hp) * NN * NN + base]     = fmaxf(a0, 0.0f) + 1e-6f;
            g_S[(size_t)(2 * hp + 1) * NN * NN + base] = fmaxf(a1, 0.0f) + 1e-6f;
        }
    }
}

// ---------------------------------------------------------------------------
// K2: split-KV attention WITHOUT online max (scores bounded; see theory).
// p = bias_lin * exp(0.125*qk); plain accumulation of O and rowsum.
// ---------------------------------------------------------------------------
#define SQ2 36
#define A_Qh 0
#define A_Ql (64 * SQ2)
#define A_Kh (2 * 64 * SQ2)
#define A_Kl (3 * 64 * SQ2)
#define A_Vh (4 * 64 * SQ2)
#define A_Vl (5 * 64 * SQ2)
#define A_PS (6 * 64 * SQ2)
#define ATTN_SMEM_U32 (A_PS + 128)

__device__ __forceinline__ void load_split_row(const float* __restrict__ gp,
                                               unsigned* sh, unsigned* sl,
                                               int row, int quarter) {
    const float* p = gp + quarter * 16;
    float4 f0 = *(const float4*)p;
    float4 f1 = *(const float4*)(p + 4);
    float4 f2 = *(const float4*)(p + 8);
    float4 f3 = *(const float4*)(p + 12);
    const float f[16] = {f0.x, f0.y, f0.z, f0.w, f1.x, f1.y, f1.z, f1.w,
                         f2.x, f2.y, f2.z, f2.w, f3.x, f3.y, f3.z, f3.w};
    unsigned hi[8], lo[8];
#pragma unroll
    for (int j = 0; j < 8; j++) {
        hi[j] = bfpack(f[2 * j], f[2 * j + 1]);
        lo[j] = bfpack(bfres(f[2 * j]), bfres(f[2 * j + 1]));
    }
    const int a = row * SQ2 + quarter * 8;
    *(uint4*)&sh[a]     = make_uint4(hi[0], hi[1], hi[2], hi[3]);
    *(uint4*)&sh[a + 4] = make_uint4(hi[4], hi[5], hi[6], hi[7]);
    *(uint4*)&sl[a]     = make_uint4(lo[0], lo[1], lo[2], lo[3]);
    *(uint4*)&sl[a + 4] = make_uint4(lo[4], lo[5], lo[6], lo[7]);
}

__global__ void __launch_bounds__(256, 3) fused_attn() {
    extern __shared__ unsigned sm[];
    unsigned* sQh = sm + A_Qh;
    unsigned* sQl = sm + A_Ql;
    unsigned* sKh = sm + A_Kh;   // K in S phase; P in PV phase
    unsigned* sKl = sm + A_Kl;
    unsigned* sVh = sm + A_Vh;   // transposed: [d][mpair]
    unsigned* sVl = sm + A_Vl;
    float* psum = (float*)(sm + A_PS);

    const int t = threadIdx.x;
    const int w = t >> 5, l = t & 31;
    const int lq = l >> 2, lr = l & 3;
    const int mrow = (w & 3) * 16;
    const int wn2  = w >> 2;
    const int ncol = wn2 * 32;

    const int h   = blockIdx.x & 7;
    const int qt  = (blockIdx.x >> 3) & 15;
    const int sp  = blockIdx.x >> 7;          // 0..3
    const int bm  = qt * BM;
    const int m0g = sp * MPART;

    const float* Qg = g_qkv + h * HD;
    const float* Kg = g_qkv + DIM + h * HD;
    const float* Vg = g_qkv + 2 * DIM + h * HD;
    const float* Bg = g_S + (size_t)h * NN * NN;

    {
        const int row = t >> 2;
        load_split_row(Qg + (size_t)(bm + row) * QKVD, sQh, sQl, row, t & 3);
    }

    float o[4][4] = {};
    float rsum0 = 0.0f, rsum1 = 0.0f;

    for (int mt = 0; mt < MPART / 64; mt++) {
        const int mbase = m0g + mt * 64;
        __syncthreads();  // prev iter fully consumed

        {
            const int row = t >> 2;
            load_split_row(Kg + (size_t)(mbase + row) * QKVD, sKh, sKl, row, t & 3);
        }
        {
            const int mp = t & 31;
            const int d0 = (t >> 5) * 8;
            const float* Vp0 = Vg + (size_t)(mbase + 2 * mp) * QKVD + d0;
            const float* Vp1 = Vp0 + QKVD;
            float4 a0 = *(const float4*)Vp0;
            float4 a1 = *(const float4*)(Vp0 + 4);
            float4 b0 = *(const float4*)Vp1;
            float4 b1 = *(const float4*)(Vp1 + 4);
            const float va[8] = {a0.x, a0.y, a0.z, a0.w, a1.x, a1.y, a1.z, a1.w};
            const float vb[8] = {b0.x, b0.y, b0.z, b0.w, b1.x, b1.y, b1.z, b1.w};
#pragma unroll
            for (int d = 0; d < 8; d++) {
                sVh[(d0 + d) * SQ2 + mp] = bfpack(va[d], vb[d]);
                sVl[(d0 + d) * SQ2 + mp] = bfpack(bfres(va[d]), bfres(vb[d]));
            }
        }
        float2 bia0[4], bia1[4];
#pragma unroll
        for (int ni = 0; ni < 4; ni++) {
            const size_t cb = (size_t)(bm + mrow + lq) * NN + mbase + ncol + ni * 8 + lr * 2;
            bia0[ni] = *(const float2*)(Bg + cb);
            bia1[ni] = *(const float2*)(Bg + cb + 8 * NN);
        }
        __syncthreads();

        // ---- S = Q K^T ----
        float sc[4][4] = {};
#pragma unroll
        for (int s = 0; s < 4; s++) {
            const int ks2 = s * 8;
            unsigned ah[4], al_[4];
            const int ab = (mrow + lq) * SQ2 + ks2 + lr;
            ah[0] = sQh[ab];  ah[1] = sQh[ab + 8 * SQ2];
            ah[2] = sQh[ab + 4]; ah[3] = sQh[ab + 8 * SQ2 + 4];
            al_[0] = sQl[ab]; al_[1] = sQl[ab + 8 * SQ2];
            al_[2] = sQl[ab + 4]; al_[3] = sQl[ab + 8 * SQ2 + 4];
#pragma unroll
            for (int ni = 0; ni < 4; ni++) {
                const int bb = (ncol + ni * 8 + lq) * SQ2 + ks2 + lr;
                unsigned bh[2] = {sKh[bb], sKh[bb + 4]};
                unsigned bl[2] = {sKl[bb], sKl[bb + 4]};
                mma_bf16(sc[ni], ah, bh);
                mma_bf16(sc[ni], ah, bl);
                mma_bf16(sc[ni], al_, bh);
            }
        }

        // ---- p = bias * exp(0.125*qk) ; row-sum ----
        float pv[4][4];
        float ls0 = 0.0f, ls1 = 0.0f;
#pragma unroll
        for (int ni = 0; ni < 4; ni++) {
            pv[ni][0] = bia0[ni].x * __expf(0.125f * sc[ni][0]);
            pv[ni][1] = bia0[ni].y * __expf(0.125f * sc[ni][1]);
            pv[ni][2] = bia1[ni].x * __expf(0.125f * sc[ni][2]);
            pv[ni][3] = bia1[ni].y * __expf(0.125f * sc[ni][3]);
            ls0 += pv[ni][0] + pv[ni][1];
            ls1 += pv[ni][2] + pv[ni][3];
        }
#pragma unroll
        for (int off = 1; off <= 2; off <<= 1) {
            ls0 += __shfl_xor_sync(0xffffffffu, ls0, off);
            ls1 += __shfl_xor_sync(0xffffffffu, ls1, off);
        }
        if (lr == 0) {
            psum[wn2 * 64 + mrow + lq] = ls0;
            psum[wn2 * 64 + mrow + lq + 8] = ls1;
        }
        __syncthreads();  // K reads done + psum visible
        rsum0 += psum[mrow + lq] + psum[64 + mrow + lq];
        rsum1 += psum[mrow + lq + 8] + psum[64 + mrow + lq + 8];

        // ---- P (hi/lo bf16x2) into the K buffers ----
#pragma unroll
        for (int ni = 0; ni < 4; ni++) {
            const int c = ncol / 2 + ni * 4 + lr;
            const int a0 = (mrow + lq) * SQ2 + c;
            const int a1 = (mrow + lq + 8) * SQ2 + c;
            sKh[a0] = bfpack(pv[ni][0], pv[ni][1]);
            sKl[a0] = bfpack(bfres(pv[ni][0]), bfres(pv[ni][1]));
            sKh[a1] = bfpack(pv[ni][2], pv[ni][3]);
            sKl[a1] = bfpack(bfres(pv[ni][2]), bfres(pv[ni][3]));
        }
        __syncthreads();  // P visible

        // ---- O += P V ----
#pragma unroll
        for (int s = 0; s < 4; s++) {
            const int ks2 = s * 8;
            unsigned ph[4], pl[4];
            const int pb = (mrow + lq) * SQ2 + ks2 + lr;
            ph[0] = sKh[pb];  ph[1] = sKh[pb + 8 * SQ2];
            ph[2] = sKh[pb + 4]; ph[3] = sKh[pb + 8 * SQ2 + 4];
            pl[0] = sKl[pb];  pl[1] = sKl[pb + 8 * SQ2];
            pl[2] = sKl[pb + 4]; pl[3] = sKl[pb + 8 * SQ2 + 4];
#pragma unroll
            for (int ni = 0; ni < 4; ni++) {
                const int vb = (ncol + ni * 8 + lq) * SQ2 + ks2 + lr;
                unsigned bh[2] = {sVh[vb], sVh[vb + 4]};
                unsigned bl[2] = {sVl[vb], sVl[vb + 4]};
                mma_bf16(o[ni], ph, bh);
                mma_bf16(o[ni], ph, bl);
                mma_bf16(o[ni], pl, bh);
            }
        }
    }

#pragma unroll
    for (int ni = 0; ni < 4; ni++) {
        const int d = ncol + ni * 8 + lr * 2;
        *(float2*)&g_Op[sp][h][bm + mrow + lq][d] = make_float2(o[ni][0], o[ni][1]);
        *(float2*)&g_Op[sp][h][bm + mrow + lq + 8][d] = make_float2(o[ni][2], o[ni][3]);
    }
    if (lr == 0 && wn2 == 0) {
        g_ls[sp][h][bm + mrow + lq] = rsum0;
        g_ls[sp][h][bm + mrow + lq + 8] = rsum1;
    }
}

// ---------------------------------------------------------------------------
// K3: merge NSPLIT partials (plain sums — all partials share implicit M=0).
// ---------------------------------------------------------------------------
__global__ void __launch_bounds__(256) merge_k(float* __restrict__ out) {
    const int w = (blockIdx.x * 8) + (threadIdx.x >> 5);
    const int lane = threadIdx.x & 31;
    const int h = w >> 10;
    const int n = w & 1023;

    float denom = 0.0f;
#pragma unroll
    for (int s = 0; s < NSPLIT; s++) denom += g_ls[s][h][n];
    const float inv = 1.0f / denom;

    float2 r = make_float2(0.0f, 0.0f);
#pragma unroll
    for (int s = 0; s < NSPLIT; s++) {
        const float2 os = *(const float2*)&g_Op[s][h][n][lane * 2];
        r.x += os.x;
        r.y += os.y;
    }
    r.x *= inv; r.y *= inv;
    *(float2*)(out + (size_t)n * DIM + h * HD + lane * 2) = r;
}

// ---------------------------------------------------------------------------
extern "C" void kernel_launch(void* const* d_in, const int* in_sizes, int n_in,
                              void* d_out, int out_size) {
    const float* x    = (const float*)d_in[0];
    const float* locs = (const float*)d_in[2];
    const float* Wqkv = (const float*)d_in[3];
    const float* Wloc = (const float*)d_in[4];
    const float* bloc = (const float*)d_in[5];
    float* out = (float*)d_out;

    cudaFuncSetAttribute(fused_attn, cudaFuncAttributeMaxDynamicSharedMemorySize,
                         ATTN_SMEM_U32 * 4);

    fused_pre<<<QKV_BLOCKS + LOC_BLOCKS, 256>>>(x, Wqkv, locs, Wloc, bloc);
    fused_attn<<<(NN / BM) * HEADS * NSPLIT, 256, ATTN_SMEM_U32 * 4>>>();
    merge_k<<<HEADS * NN / 8, 256>>>(out);
}

// round 17
// speedup vs baseline: 1.4507x; 1.0151x over previous
#include <cuda_runtime.h>
#include <cuda_bf16.h>
#include <math.h>

#define NN 1024
#define DIM 512
#define QKVD 1536
#define HEADS 8
#define HD 64
#define BM 64
#define NSPLIT 4
#define MPART (NN / NSPLIT)

#define QKV_MT 128
#define QKV_NT 64
#define QKV_BLOCKS ((NN / QKV_MT) * (QKVD / QKV_NT))   // 192
#define LOC_BLOCKS (NN * NN / 512)                      // 2048 (2 pairs/thread)

// Scratch (static device allocation only).
__device__ float g_qkv[NN * QKVD];
__device__ float g_S[(size_t)HEADS * NN * NN];   // LINEAR bias: relu(.)+1e-6
__device__ float g_Op[NSPLIT][HEADS][NN][HD];
__device__ float g_ls[NSPLIT][HEADS][NN];

// ---------------------------------------------------------------------------
// helpers
// ---------------------------------------------------------------------------
__device__ __forceinline__ unsigned cvt_tf32(float f) {
    unsigned u;
    asm("cvt.rna.tf32.f32 %0, %1;" : "=r"(u) : "f"(f));
    return u;
}
__device__ __forceinline__ void split_tf32(float f, unsigned& hi, unsigned& lo) {
    hi = cvt_tf32(f);
    lo = cvt_tf32(f - __uint_as_float(hi));
}
__device__ __forceinline__ void mma_tf32(float* c, const unsigned* a, const unsigned* b) {
    asm volatile(
        "mma.sync.aligned.m16n8k8.row.col.f32.tf32.tf32.f32 "
        "{%0,%1,%2,%3}, {%4,%5,%6,%7}, {%8,%9}, {%0,%1,%2,%3};"
        : "+f"(c[0]), "+f"(c[1]), "+f"(c[2]), "+f"(c[3])
        : "r"(a[0]), "r"(a[1]), "r"(a[2]), "r"(a[3]), "r"(b[0]), "r"(b[1]));
}
__device__ __forceinline__ void mma_bf16(float* c, const unsigned* a, const unsigned* b) {
    asm volatile(
        "mma.sync.aligned.m16n8k16.row.col.f32.bf16.bf16.f32 "
        "{%0,%1,%2,%3}, {%4,%5,%6,%7}, {%8,%9}, {%0,%1,%2,%3};"
        : "+f"(c[0]), "+f"(c[1]), "+f"(c[2]), "+f"(c[3])
        : "r"(a[0]), "r"(a[1]), "r"(a[2]), "r"(a[3]), "r"(b[0]), "r"(b[1]));
}
__device__ __forceinline__ unsigned bfpack(float lo_e, float hi_e) {
    unsigned r;
    asm("cvt.rn.bf16x2.f32 %0, %1, %2;" : "=r"(r) : "f"(hi_e), "f"(lo_e));
    return r;
}
__device__ __forceinline__ float bfres(float f) {
    return f - __bfloat162float(__float2bfloat16(f));
}
__device__ __forceinline__ unsigned long long pack2(float lo, float hi) {
    unsigned long long r;
    asm("mov.b64 %0, {%1, %2};" : "=l"(r) : "f"(lo), "f"(hi));
    return r;
}
__device__ __forceinline__ void unpack2(unsigned long long v, float& lo, float& hi) {
    asm("mov.b64 {%0, %1}, %2;" : "=f"(lo), "=f"(hi) : "l"(v));
}
__device__ __forceinline__ unsigned long long fma2(unsigned long long a,
                                                   unsigned long long b,
                                                   unsigned long long c) {
    unsigned long long d;
    asm("fma.rn.f32x2 %0, %1, %2, %3;" : "=l"(d) : "l"(a), "l"(b), "l"(c));
    return d;
}

// ---------------------------------------------------------------------------
// K1 (fused): blocks [0,192) = tf32 QKV GEMM; [192, 2240) = loc bias
// (2 pairs per thread for ILP + LDS amortization).
// ---------------------------------------------------------------------------
struct SmemQkv {
    float As[QKV_MT][20];
    float Bs[QKV_NT][20];
};
struct SmemLoc {
    unsigned long long sW2[64][4];
    float sb[8];
};

__global__ void __launch_bounds__(256, 3) fused_pre(const float* __restrict__ x,
                                                    const float* __restrict__ W,
                                                    const float* __restrict__ locs,
                                                    const float* __restrict__ Wl,
                                                    const float* __restrict__ bl) {
    __shared__ char smem_raw[sizeof(SmemQkv) > sizeof(SmemLoc) ? sizeof(SmemQkv)
                                                               : sizeof(SmemLoc)];
    const int t = threadIdx.x;

    if (blockIdx.x < QKV_BLOCKS) {
        SmemQkv* s = (SmemQkv*)smem_raw;
        const int qb = blockIdx.x;
        const int bm = (qb % (NN / QKV_MT)) * QKV_MT;
        const int bn = (qb / (NN / QKV_MT)) * QKV_NT;
        const int w  = t >> 5, l = t & 31;
        const int wm = (w & 3) * 32;
        const int wn = (w >> 2) * 32;
        const int lq = l >> 2, lr = l & 3;

        const int arow = t >> 1;
        const int akc  = (t & 1) * 8;
        const float* Ap = x + (size_t)(bm + arow) * DIM + akc;
        const float* Bp = W + (size_t)(bn + (arow & 63)) * DIM + akc;

        float4 ra0 = *(const float4*)Ap;
        float4 ra1 = *(const float4*)(Ap + 4);
        float4 rb0 = make_float4(0, 0, 0, 0), rb1 = rb0;
        if (t < 128) { rb0 = *(const float4*)Bp; rb1 = *(const float4*)(Bp + 4); }

        float acc[2][4][4] = {};

        for (int kk = 0; kk < DIM; kk += 16) {
            __syncthreads();
            *(float4*)&s->As[arow][akc]     = ra0;
            *(float4*)&s->As[arow][akc + 4] = ra1;
            if (t < 128) {
                *(float4*)&s->Bs[arow & 63][akc]     = rb0;
                *(float4*)&s->Bs[arow & 63][akc + 4] = rb1;
            }
            __syncthreads();
            if (kk + 16 < DIM) {
                ra0 = *(const float4*)(Ap + kk + 16);
                ra1 = *(const float4*)(Ap + kk + 20);
                if (t < 128) {
                    rb0 = *(const float4*)(Bp + kk + 16);
                    rb1 = *(const float4*)(Bp + kk + 20);
                }
            }
#pragma unroll
            for (int ks = 0; ks < 16; ks += 8) {
                unsigned ahi[2][4], alo[2][4];
#pragma unroll
                for (int mi = 0; mi < 2; mi++) {
                    const int r = wm + mi * 16;
                    split_tf32(s->As[r + lq][ks + lr],          ahi[mi][0], alo[mi][0]);
                    split_tf32(s->As[r + lq + 8][ks + lr],      ahi[mi][1], alo[mi][1]);
                    split_tf32(s->As[r + lq][ks + lr + 4],      ahi[mi][2], alo[mi][2]);
                    split_tf32(s->As[r + lq + 8][ks + lr + 4],  ahi[mi][3], alo[mi][3]);
                }
#pragma unroll
                for (int ni = 0; ni < 4; ni++) {
                    unsigned bhi[2], blo[2];
                    const int c = wn + ni * 8 + lq;
                    split_tf32(s->Bs[c][ks + lr],     bhi[0], blo[0]);
                    split_tf32(s->Bs[c][ks + lr + 4], bhi[1], blo[1]);
#pragma unroll
                    for (int mi = 0; mi < 2; mi++) {
                        mma_tf32(acc[mi][ni], ahi[mi], bhi);
                        mma_tf32(acc[mi][ni], ahi[mi], blo);
                        mma_tf32(acc[mi][ni], alo[mi], bhi);
                    }
                }
            }
        }
#pragma unroll
        for (int mi = 0; mi < 2; mi++)
#pragma unroll
            for (int ni = 0; ni < 4; ni++) {
                const int r = bm + wm + mi * 16 + lq;
                const int c = bn + wn + ni * 8 + lr * 2;
                *(float2*)&g_qkv[(size_t)r * QKVD + c] =
                    make_float2(acc[mi][ni][0], acc[mi][ni][1]);
                *(float2*)&g_qkv[(size_t)(r + 8) * QKVD + c] =
                    make_float2(acc[mi][ni][2], acc[mi][ni][3]);
            }
    } else {
        SmemLoc* s = (SmemLoc*)smem_raw;
        {
            const int f = t >> 2, hp = t & 3;
            s->sW2[f][hp] = pack2(Wl[(2 * hp) * 64 + f], Wl[(2 * hp + 1) * 64 + f]);
        }
        if (t < 8) s->sb[t] = bl[t];
        __syncthreads();

        const int lid = blockIdx.x - QKV_BLOCKS;   // 0..2047
        const int n = lid >> 1;
        const int m0 = (lid & 1) * 512 + t;        // pair A
        const int m1 = m0 + 256;                   // pair B

        const float4 bn = ((const float4*)locs)[n];
        const float4 bmA = ((const float4*)locs)[m0];
        const float4 bmB = ((const float4*)locs)[m1];
        const float wn = bn.z - bn.x + 1.0f, hn = bn.w - bn.y + 1.0f;
        const float cxn = 0.5f * (bn.x + bn.z), cyn = 0.5f * (bn.y + bn.w);

        float posA[4], posB[4];
        {
            const float wmA = bmA.z - bmA.x + 1.0f, hmA = bmA.w - bmA.y + 1.0f;
            const float cxA = 0.5f * (bmA.x + bmA.z), cyA = 0.5f * (bmA.y + bmA.w);
            posA[0] = __logf(fmaxf(fabsf((cxn - cxA) / wn), 1e-3f));
            posA[1] = __logf(fmaxf(fabsf((cyn - cyA) / hn), 1e-3f));
            posA[2] = __logf(wmA / wn);
            posA[3] = __logf(hmA / hn);
            const float wmB = bmB.z - bmB.x + 1.0f, hmB = bmB.w - bmB.y + 1.0f;
            const float cxB = 0.5f * (bmB.x + bmB.z), cyB = 0.5f * (bmB.y + bmB.w);
            posB[0] = __logf(fmaxf(fabsf((cxn - cxB) / wn), 1e-3f));
            posB[1] = __logf(fmaxf(fabsf((cyn - cyB) / hn), 1e-3f));
            posB[2] = __logf(wmB / wn);
            posB[3] = __logf(hmB / hn);
        }

        const float invd[8] = {100.0f, 42.1696503f, 17.7827941f, 7.49894209f,
                               3.16227766f, 1.33352143f, 0.562341325f, 0.237137371f};

        unsigned long long accA[4], accB[4];
#pragma unroll
        for (int hp = 0; hp < 4; hp++) {
            accA[hp] = pack2(s->sb[2 * hp], s->sb[2 * hp + 1]);
            accB[hp] = accA[hp];
        }

#pragma unroll
        for (int g = 0; g < 4; g++) {
#pragma unroll
            for (int j = 0; j < 8; j++) {
                float snA, csA, snB, csB;
                __sincosf(posA[g] * invd[j], &snA, &csA);
                __sincosf(posB[g] * invd[j], &snB, &csB);
                const unsigned long long ssA = pack2(snA, snA);
                const unsigned long long ccA = pack2(csA, csA);
                const unsigned long long ssB = pack2(snB, snB);
                const unsigned long long ccB = pack2(csB, csB);
                const ulonglong2* wsp = (const ulonglong2*)s->sW2[g * 16 + j];
                const ulonglong2* wcp = (const ulonglong2*)s->sW2[g * 16 + 8 + j];
                const ulonglong2 w01 = wsp[0], w23 = wsp[1];
                const ulonglong2 c01 = wcp[0], c23 = wcp[1];
                accA[0] = fma2(ssA, w01.x, accA[0]);
                accB[0] = fma2(ssB, w01.x, accB[0]);
                accA[1] = fma2(ssA, w01.y, accA[1]);
                accB[1] = fma2(ssB, w01.y, accB[1]);
                accA[2] = fma2(ssA, w23.x, accA[2]);
                accB[2] = fma2(ssB, w23.x, accB[2]);
                accA[3] = fma2(ssA, w23.y, accA[3]);
                accB[3] = fma2(ssB, w23.y, accB[3]);
                accA[0] = fma2(ccA, c01.x, accA[0]);
                accB[0] = fma2(ccB, c01.x, accB[0]);
                accA[1] = fma2(ccA, c01.y, accA[1]);
                accB[1] = fma2(ccB, c01.y, accB[1]);
                accA[2] = fma2(ccA, c23.x, accA[2]);
                accB[2] = fma2(ccB, c23.x, accB[2]);
                accA[3] = fma2(ccA, c23.y, accA[3]);
                accB[3] = fma2(ccB, c23.y, accB[3]);
            }
        }
        const size_t baseA = (size_t)n * NN + m0;
        const size_t baseB = (size_t)n * NN + m1;
#pragma unroll
        for (int hp = 0; hp < 4; hp++) {
            float a0, a1, b0, b1;
            unpack2(accA[hp], a0, a1);
            unpack2(accB[hp], b0, b1);
            g_S[(size_t)(2 * hp) * NN * NN + baseA]     = fmaxf(a0, 0.0f) + 1e-6f;
            g_S[(size_t)(2 * hp + 1) * NN * NN + baseA] = fmaxf(a1, 0.0f) + 1e-6f;
            g_S[(size_t)(2 * hp) * NN * NN + baseB]     = fmaxf(b0, 0.0f) + 1e-6f;
            g_S[(size_t)(2 * hp + 1) * NN * NN + baseB] = fmaxf(b1, 0.0f) + 1e-6f;
        }
    }
}

// ---------------------------------------------------------------------------
// K2: split-KV attention WITHOUT online max (scores bounded).
// ---------------------------------------------------------------------------
#define SQ2 36
#define A_Qh 0
#define A_Ql (64 * SQ2)
#define A_Kh (2 * 64 * SQ2)
#define A_Kl (3 * 64 * SQ2)
#define A_Vh (4 * 64 * SQ2)
#define A_Vl (5 * 64 * SQ2)
#define A_PS (6 * 64 * SQ2)
#define ATTN_SMEM_U32 (A_PS + 128)

__device__ __forceinline__ void load_split_row(const float* __restrict__ gp,
                                               unsigned* sh, unsigned* sl,
                                               int row, int quarter) {
    const float* p = gp + quarter * 16;
    float4 f0 = *(const float4*)p;
    float4 f1 = *(const float4*)(p + 4);
    float4 f2 = *(const float4*)(p + 8);
    float4 f3 = *(const float4*)(p + 12);
    const float f[16] = {f0.x, f0.y, f0.z, f0.w, f1.x, f1.y, f1.z, f1.w,
                         f2.x, f2.y, f2.z, f2.w, f3.x, f3.y, f3.z, f3.w};
    unsigned hi[8], lo[8];
#pragma unroll
    for (int j = 0; j < 8; j++) {
        hi[j] = bfpack(f[2 * j], f[2 * j + 1]);
        lo[j] = bfpack(bfres(f[2 * j]), bfres(f[2 * j + 1]));
    }
    const int a = row * SQ2 + quarter * 8;
    *(uint4*)&sh[a]     = make_uint4(hi[0], hi[1], hi[2], hi[3]);
    *(uint4*)&sh[a + 4] = make_uint4(hi[4], hi[5], hi[6], hi[7]);
    *(uint4*)&sl[a]     = make_uint4(lo[0], lo[1], lo[2], lo[3]);
    *(uint4*)&sl[a + 4] = make_uint4(lo[4], lo[5], lo[6], lo[7]);
}

__global__ void __launch_bounds__(256, 3) fused_attn() {
    extern __shared__ unsigned sm[];
    unsigned* sQh = sm + A_Qh;
    unsigned* sQl = sm + A_Ql;
    unsigned* sKh = sm + A_Kh;
    unsigned* sKl = sm + A_Kl;
    unsigned* sVh = sm + A_Vh;
    unsigned* sVl = sm + A_Vl;
    float* psum = (float*)(sm + A_PS);

    const int t = threadIdx.x;
    const int w = t >> 5, l = t & 31;
    const int lq = l >> 2, lr = l & 3;
    const int mrow = (w & 3) * 16;
    const int wn2  = w >> 2;
    const int ncol = wn2 * 32;

    const int h   = blockIdx.x & 7;
    const int qt  = (blockIdx.x >> 3) & 15;
    const int sp  = blockIdx.x >> 7;
    const int bm  = qt * BM;
    const int m0g = sp * MPART;

    const float* Qg = g_qkv + h * HD;
    const float* Kg = g_qkv + DIM + h * HD;
    const float* Vg = g_qkv + 2 * DIM + h * HD;
    const float* Bg = g_S + (size_t)h * NN * NN;

    {
        const int row = t >> 2;
        load_split_row(Qg + (size_t)(bm + row) * QKVD, sQh, sQl, row, t & 3);
    }

    float o[4][4] = {};
    float rsum0 = 0.0f, rsum1 = 0.0f;

    for (int mt = 0; mt < MPART / 64; mt++) {
        const int mbase = m0g + mt * 64;
        __syncthreads();

        {
            const int row = t >> 2;
            load_split_row(Kg + (size_t)(mbase + row) * QKVD, sKh, sKl, row, t & 3);
        }
        {
            const int mp = t & 31;
            const int d0 = (t >> 5) * 8;
            const float* Vp0 = Vg + (size_t)(mbase + 2 * mp) * QKVD + d0;
            const float* Vp1 = Vp0 + QKVD;
            float4 a0 = *(const float4*)Vp0;
            float4 a1 = *(const float4*)(Vp0 + 4);
            float4 b0 = *(const float4*)Vp1;
            float4 b1 = *(const float4*)(Vp1 + 4);
            const float va[8] = {a0.x, a0.y, a0.z, a0.w, a1.x, a1.y, a1.z, a1.w};
            const float vb[8] = {b0.x, b0.y, b0.z, b0.w, b1.x, b1.y, b1.z, b1.w};
#pragma unroll
            for (int d = 0; d < 8; d++) {
                sVh[(d0 + d) * SQ2 + mp] = bfpack(va[d], vb[d]);
                sVl[(d0 + d) * SQ2 + mp] = bfpack(bfres(va[d]), bfres(vb[d]));
            }
        }
        float2 bia0[4], bia1[4];
#pragma unroll
        for (int ni = 0; ni < 4; ni++) {
            const size_t cb = (size_t)(bm + mrow + lq) * NN + mbase + ncol + ni * 8 + lr * 2;
            bia0[ni] = *(const float2*)(Bg + cb);
            bia1[ni] = *(const float2*)(Bg + cb + 8 * NN);
        }
        __syncthreads();

        float sc[4][4] = {};
#pragma unroll
        for (int s = 0; s < 4; s++) {
            const int ks2 = s * 8;
            unsigned ah[4], al_[4];
            const int ab = (mrow + lq) * SQ2 + ks2 + lr;
            ah[0] = sQh[ab];  ah[1] = sQh[ab + 8 * SQ2];
            ah[2] = sQh[ab + 4]; ah[3] = sQh[ab + 8 * SQ2 + 4];
            al_[0] = sQl[ab]; al_[1] = sQl[ab + 8 * SQ2];
            al_[2] = sQl[ab + 4]; al_[3] = sQl[ab + 8 * SQ2 + 4];
#pragma unroll
            for (int ni = 0; ni < 4; ni++) {
                const int bb = (ncol + ni * 8 + lq) * SQ2 + ks2 + lr;
                unsigned bh[2] = {sKh[bb], sKh[bb + 4]};
                unsigned bl[2] = {sKl[bb], sKl[bb + 4]};
                mma_bf16(sc[ni], ah, bh);
                mma_bf16(sc[ni], ah, bl);
                mma_bf16(sc[ni], al_, bh);
            }
        }

        float pv[4][4];
        float ls0 = 0.0f, ls1 = 0.0f;
#pragma unroll
        for (int ni = 0; ni < 4; ni++) {
            pv[ni][0] = bia0[ni].x * __expf(0.125f * sc[ni][0]);
            pv[ni][1] = bia0[ni].y * __expf(0.125f * sc[ni][1]);
            pv[ni][2] = bia1[ni].x * __expf(0.125f * sc[ni][2]);
            pv[ni][3] = bia1[ni].y * __expf(0.125f * sc[ni][3]);
            ls0 += pv[ni][0] + pv[ni][1];
            ls1 += pv[ni][2] + pv[ni][3];
        }
#pragma unroll
        for (int off = 1; off <= 2; off <<= 1) {
            ls0 += __shfl_xor_sync(0xffffffffu, ls0, off);
            ls1 += __shfl_xor_sync(0xffffffffu, ls1, off);
        }
        if (lr == 0) {
            psum[wn2 * 64 + mrow + lq] = ls0;
            psum[wn2 * 64 + mrow + lq + 8] = ls1;
        }
        __syncthreads();
        rsum0 += psum[mrow + lq] + psum[64 + mrow + lq];
        rsum1 += psum[mrow + lq + 8] + psum[64 + mrow + lq + 8];

#pragma unroll
        for (int ni = 0; ni < 4; ni++) {
            const int c = ncol / 2 + ni * 4 + lr;
            const int a0 = (mrow + lq) * SQ2 + c;
            const int a1 = (mrow + lq + 8) * SQ2 + c;
            sKh[a0] = bfpack(pv[ni][0], pv[ni][1]);
            sKl[a0] = bfpack(bfres(pv[ni][0]), bfres(pv[ni][1]));
            sKh[a1] = bfpack(pv[ni][2], pv[ni][3]);
            sKl[a1] = bfpack(bfres(pv[ni][2]), bfres(pv[ni][3]));
        }
        __syncthreads();

#pragma unroll
        for (int s = 0; s < 4; s++) {
            const int ks2 = s * 8;
            unsigned ph[4], pl[4];
            const int pb = (mrow + lq) * SQ2 + ks2 + lr;
            ph[0] = sKh[pb];  ph[1] = sKh[pb + 8 * SQ2];
            ph[2] = sKh[pb + 4]; ph[3] = sKh[pb + 8 * SQ2 + 4];
            pl[0] = sKl[pb];  pl[1] = sKl[pb + 8 * SQ2];
            pl[2] = sKl[pb + 4]; pl[3] = sKl[pb + 8 * SQ2 + 4];
#pragma unroll
            for (int ni = 0; ni < 4; ni++) {
                const int vb = (ncol + ni * 8 + lq) * SQ2 + ks2 + lr;
                unsigned bh[2] = {sVh[vb], sVh[vb + 4]};
                unsigned bl[2] = {sVl[vb], sVl[vb + 4]};
                mma_bf16(o[ni], ph, bh);
                mma_bf16(o[ni], ph, bl);
                mma_bf16(o[ni], pl, bh);
            }
        }
    }

#pragma unroll
    for (int ni = 0; ni < 4; ni++) {
        const int d = ncol + ni * 8 + lr * 2;
        *(float2*)&g_Op[sp][h][bm + mrow + lq][d] = make_float2(o[ni][0], o[ni][1]);
        *(float2*)&g_Op[sp][h][bm + mrow + lq + 8][d] = make_float2(o[ni][2], o[ni][3]);
    }
    if (lr == 0 && wn2 == 0) {
        g_ls[sp][h][bm + mrow + lq] = rsum0;
        g_ls[sp][h][bm + mrow + lq + 8] = rsum1;
    }
}

// ---------------------------------------------------------------------------
// K3: merge NSPLIT partials (plain sums).
// ---------------------------------------------------------------------------
__global__ void __launch_bounds__(256) merge_k(float* __restrict__ out) {
    const int w = (blockIdx.x * 8) + (threadIdx.x >> 5);
    const int lane = threadIdx.x & 31;
    const int h = w >> 10;
    const int n = w & 1023;

    float denom = 0.0f;
#pragma unroll
    for (int s = 0; s < NSPLIT; s++) denom += g_ls[s][h][n];
    const float inv = 1.0f / denom;

    float2 r = make_float2(0.0f, 0.0f);
#pragma unroll
    for (int s = 0; s < NSPLIT; s++) {
        const float2 os = *(const float2*)&g_Op[s][h][n][lane * 2];
        r.x += os.x;
        r.y += os.y;
    }
    r.x *= inv; r.y *= inv;
    *(float2*)(out + (size_t)n * DIM + h * HD + lane * 2) = r;
}

// ---------------------------------------------------------------------------
extern "C" void kernel_launch(void* const* d_in, const int* in_sizes, int n_in,
                              void* d_out, int out_size) {
    const float* x    = (const float*)d_in[0];
    const float* locs = (const float*)d_in[2];
    const float* Wqkv = (const float*)d_in[3];
    const float* Wloc = (const float*)d_in[4];
    const float* bloc = (const float*)d_in[5];
    float* out = (float*)d_out;

    cudaFuncSetAttribute(fused_attn, cudaFuncAttributeMaxDynamicSharedMemorySize,
                         ATTN_SMEM_U32 * 4);

    fused_pre<<<QKV_BLOCKS + LOC_BLOCKS, 256>>>(x, Wqkv, locs, Wloc, bloc);
    fused_attn<<<(NN / BM) * HEADS * NSPLIT, 256, ATTN_SMEM_U32 * 4>>>();
    merge_k<<<HEADS * NN / 8, 256>>>(out);
}